// round 5
// baseline (speedup 1.0000x reference)
#include <cuda_runtime.h>
#include <math.h>

// Problem constants
#define BB   2
#define LL   2048
#define DD   2048
#define HH   16
#define KVH  4
#define EE   128
#define ML   (BB*LL)        // 4096 rows total
#define HE   (HH*EE)        // 2048
#define KVE  (KVH*EE)       // 512

// -------- scratch (device globals; no allocation allowed) --------
__device__ float g_Q[ML*HE];      // [B*L, H*E]
__device__ float g_K[ML*KVE];     // [B*L, KV*E]
__device__ float g_V[ML*KVE];     // [B*L, KV*E]
__device__ float g_CTX[ML*HE];    // attention output
__device__ float g_Y[ML*DD];      // pre-GELU O-proj output

// ============================================================
// SGEMM: C[M,N] = A[M,K] @ B[K,N] + bias[N]   (row-major all)
// 128x128 block tile, BK=8, 256 threads, 8x8 per thread.
// Requires M%128==0, N%128==0, K%8==0 (true for all our shapes).
// ============================================================
__global__ __launch_bounds__(256)
void sgemm_bias(const float* __restrict__ A, const float* __restrict__ B,
                const float* __restrict__ bias, float* __restrict__ C,
                int M, int N, int K)
{
    __shared__ float As[8][128];   // transposed A tile: As[k][m]
    __shared__ float Bs[8][128];   // Bs[k][n]

    const int tid = threadIdx.x;
    const int bx = blockIdx.x, by = blockIdx.y;
    const int tx = tid & 15, ty = tid >> 4;

    const int a_r = tid >> 1, a_c = (tid & 1) * 4;      // A: 128 rows x 8 cols (float4)
    const int b_r = tid >> 5, b_c = (tid & 31) * 4;     // B: 8 rows x 128 cols (float4)

    const float* Ag = A + ((size_t)(by*128 + a_r))*K + a_c;
    const float* Bg = B + (size_t)b_r*N + bx*128 + b_c;

    float acc[8][8];
    #pragma unroll
    for (int a = 0; a < 8; a++)
        #pragma unroll
        for (int b2 = 0; b2 < 8; b2++) acc[a][b2] = 0.f;

    for (int k0 = 0; k0 < K; k0 += 8) {
        float4 av = *(const float4*)(Ag + k0);
        As[a_c+0][a_r] = av.x;
        As[a_c+1][a_r] = av.y;
        As[a_c+2][a_r] = av.z;
        As[a_c+3][a_r] = av.w;
        *(float4*)&Bs[b_r][b_c] = *(const float4*)(Bg + (size_t)k0*N);
        __syncthreads();

        #pragma unroll
        for (int k = 0; k < 8; ++k) {
            float ar[8], br[8];
            *(float4*)(ar)   = *(float4*)&As[k][ty*8];
            *(float4*)(ar+4) = *(float4*)&As[k][ty*8+4];
            *(float4*)(br)   = *(float4*)&Bs[k][tx*8];
            *(float4*)(br+4) = *(float4*)&Bs[k][tx*8+4];
            #pragma unroll
            for (int a = 0; a < 8; a++)
                #pragma unroll
                for (int b2 = 0; b2 < 8; b2++)
                    acc[a][b2] += ar[a]*br[b2];
        }
        __syncthreads();
    }

    #pragma unroll
    for (int a = 0; a < 8; a++) {
        const int row = by*128 + ty*8 + a;
        #pragma unroll
        for (int b2 = 0; b2 < 8; b2 += 4) {
            const int col = bx*128 + tx*8 + b2;
            float4 o;
            o.x = acc[a][b2+0] + bias[col+0];
            o.y = acc[a][b2+1] + bias[col+1];
            o.z = acc[a][b2+2] + bias[col+2];
            o.w = acc[a][b2+3] + bias[col+3];
            *(float4*)(C + (size_t)row*N + col) = o;
        }
    }
}

// ============================================================
// Flash attention (causal, GQA): per block = one (b,h) x 64-query tile.
// Br=Bc=64, E=128. Online softmax, O in registers (4 rows x 8 cols / thread).
// ============================================================
#define FL_SMEM_FLOATS (64*128 + 128*68 + 64*128 + 64*68 + 192)

__global__ __launch_bounds__(256)
void flash_kernel(const float* __restrict__ Q, const float* __restrict__ K,
                  const float* __restrict__ V, float* __restrict__ ctx)
{
    extern __shared__ float sm[];
    float* Qs  = sm;                  // [64][128]  scaled Q
    float* Kst = Qs  + 64*128;        // [128][68]  K transposed (e-major), padded
    float* Vs  = Kst + 128*68;        // [64][128]
    float* Ss  = Vs  + 64*128;        // [64][68]   scores / probabilities
    float* mrow = Ss + 64*68;         // [64]
    float* lrow = mrow + 64;          // [64]
    float* arow = lrow + 64;          // [64]

    const int tid = threadIdx.x;
    const int bh  = blockIdx.y;
    const int b   = bh / HH, h = bh % HH;
    const int kv  = h % KVH;                 // GQA: head h reads kv-head h%KV
    const int qb  = blockIdx.x * 64;
    const float scale = 0.08838834764831845f;   // 1/sqrt(128)

    // load Q tile (pre-scaled)
    {
        const float* Qg = Q + ((size_t)(b*LL + qb))*HE + h*EE;
        for (int t = tid; t < 64*32; t += 256) {
            int r = t >> 5, c4 = (t & 31) << 2;
            float4 v = *(const float4*)(Qg + (size_t)r*HE + c4);
            v.x *= scale; v.y *= scale; v.z *= scale; v.w *= scale;
            *(float4*)(Qs + r*128 + c4) = v;
        }
    }
    if (tid < 64) { mrow[tid] = -INFINITY; lrow[tid] = 0.f; }

    float O[4][8];
    #pragma unroll
    for (int a = 0; a < 4; a++)
        #pragma unroll
        for (int e = 0; e < 8; e++) O[a][e] = 0.f;

    const int i = tid >> 4, j = tid & 15;   // 16x16 thread grid
    const int r0 = i*4;                     // 4 query rows per thread
    const int c0 = j*4;                     // 4 key cols (S phase)
    const int e0 = j*8;                     // 8 head dims (O phase)

    const int ntiles = qb/64 + 1;           // causal
    for (int tkv = 0; tkv < ntiles; ++tkv) {
        const int kb = tkv * 64;
        __syncthreads();   // protect smem reuse across iterations (and Q load, 1st iter)

        // load K (transposed into Kst[e][c]) and V (row-major)
        const float* Kg = K + ((size_t)(b*LL + kb))*KVE + kv*EE;
        const float* Vg = V + ((size_t)(b*LL + kb))*KVE + kv*EE;
        for (int t = tid; t < 64*32; t += 256) {
            int r = t >> 5, c4 = (t & 31) << 2;
            float4 vk = *(const float4*)(Kg + (size_t)r*KVE + c4);
            Kst[(c4+0)*68 + r] = vk.x;
            Kst[(c4+1)*68 + r] = vk.y;
            Kst[(c4+2)*68 + r] = vk.z;
            Kst[(c4+3)*68 + r] = vk.w;
            *(float4*)(Vs + r*128 + c4) = *(const float4*)(Vg + (size_t)r*KVE + c4);
        }
        __syncthreads();

        // S = (Q*scale) @ K^T : each thread computes a 4x4 block
        float acc[4][4];
        #pragma unroll
        for (int a = 0; a < 4; a++)
            #pragma unroll
            for (int c = 0; c < 4; c++) acc[a][c] = 0.f;

        #pragma unroll 4
        for (int e = 0; e < 128; ++e) {
            const float q0 = Qs[(r0+0)*128 + e];
            const float q1 = Qs[(r0+1)*128 + e];
            const float q2 = Qs[(r0+2)*128 + e];
            const float q3 = Qs[(r0+3)*128 + e];
            const float4 kvv = *(const float4*)(Kst + e*68 + c0);
            acc[0][0] += q0*kvv.x; acc[0][1] += q0*kvv.y; acc[0][2] += q0*kvv.z; acc[0][3] += q0*kvv.w;
            acc[1][0] += q1*kvv.x; acc[1][1] += q1*kvv.y; acc[1][2] += q1*kvv.z; acc[1][3] += q1*kvv.w;
            acc[2][0] += q2*kvv.x; acc[2][1] += q2*kvv.y; acc[2][2] += q2*kvv.z; acc[2][3] += q2*kvv.w;
            acc[3][0] += q3*kvv.x; acc[3][1] += q3*kvv.y; acc[3][2] += q3*kvv.z; acc[3][3] += q3*kvv.w;
        }

        const bool diag = (kb == qb);
        #pragma unroll
        for (int a = 0; a < 4; a++)
            #pragma unroll
            for (int c = 0; c < 4; c++) {
                float v = acc[a][c];
                if (diag && (c0 + c) > (r0 + a)) v = -1e30f;
                Ss[(r0+a)*68 + c0 + c] = v;
            }
        __syncthreads();

        // online softmax per row (64 threads)
        if (tid < 64) {
            const int r = tid;
            float mx = -1e30f;
            #pragma unroll 8
            for (int c = 0; c < 64; ++c) mx = fmaxf(mx, Ss[r*68 + c]);
            const float mold = mrow[r];
            const float mnew = fmaxf(mold, mx);
            const float al   = __expf(mold - mnew);   // 0 on first tile
            float s = 0.f;
            #pragma unroll 8
            for (int c = 0; c < 64; ++c) {
                float p = __expf(Ss[r*68 + c] - mnew);
                Ss[r*68 + c] = p;
                s += p;
            }
            mrow[r] = mnew;
            lrow[r] = lrow[r]*al + s;
            arow[r] = al;
        }
        __syncthreads();

        // O = O*alpha + P @ V
        const float al0 = arow[r0+0], al1 = arow[r0+1], al2 = arow[r0+2], al3 = arow[r0+3];
        #pragma unroll
        for (int e = 0; e < 8; e++) {
            O[0][e] *= al0; O[1][e] *= al1; O[2][e] *= al2; O[3][e] *= al3;
        }
        #pragma unroll 2
        for (int c = 0; c < 64; ++c) {
            const float p0 = Ss[(r0+0)*68 + c];
            const float p1 = Ss[(r0+1)*68 + c];
            const float p2 = Ss[(r0+2)*68 + c];
            const float p3 = Ss[(r0+3)*68 + c];
            const float4 va = *(const float4*)(Vs + c*128 + e0);
            const float4 vb = *(const float4*)(Vs + c*128 + e0 + 4);
            O[0][0]+=p0*va.x; O[0][1]+=p0*va.y; O[0][2]+=p0*va.z; O[0][3]+=p0*va.w;
            O[0][4]+=p0*vb.x; O[0][5]+=p0*vb.y; O[0][6]+=p0*vb.z; O[0][7]+=p0*vb.w;
            O[1][0]+=p1*va.x; O[1][1]+=p1*va.y; O[1][2]+=p1*va.z; O[1][3]+=p1*va.w;
            O[1][4]+=p1*vb.x; O[1][5]+=p1*vb.y; O[1][6]+=p1*vb.z; O[1][7]+=p1*vb.w;
            O[2][0]+=p2*va.x; O[2][1]+=p2*va.y; O[2][2]+=p2*va.z; O[2][3]+=p2*va.w;
            O[2][4]+=p2*vb.x; O[2][5]+=p2*vb.y; O[2][6]+=p2*vb.z; O[2][7]+=p2*vb.w;
            O[3][0]+=p3*va.x; O[3][1]+=p3*va.y; O[3][2]+=p3*va.z; O[3][3]+=p3*va.w;
            O[3][4]+=p3*vb.x; O[3][5]+=p3*vb.y; O[3][6]+=p3*vb.z; O[3][7]+=p3*vb.w;
        }
    }

    // write out ctx (divide by l)
    float* Cg = ctx + ((size_t)(b*LL + qb))*HE + h*EE;
    #pragma unroll
    for (int a = 0; a < 4; a++) {
        const float inv = 1.f / lrow[r0+a];
        float4 oa, ob;
        oa.x = O[a][0]*inv; oa.y = O[a][1]*inv; oa.z = O[a][2]*inv; oa.w = O[a][3]*inv;
        ob.x = O[a][4]*inv; ob.y = O[a][5]*inv; ob.z = O[a][6]*inv; ob.w = O[a][7]*inv;
        *(float4*)(Cg + (size_t)(r0+a)*HE + e0)     = oa;
        *(float4*)(Cg + (size_t)(r0+a)*HE + e0 + 4) = ob;
    }
}

// ============================================================
// Epilogue: out = LayerNorm(x + gelu_erf(ypre)) * gamma + beta
// One block per row, 256 threads, 8 elements/thread (D=2048).
// ============================================================
__global__ __launch_bounds__(256)
void epilogue_ln(const float* __restrict__ x, const float* __restrict__ ypre,
                 const float* __restrict__ gamma, const float* __restrict__ beta,
                 float* __restrict__ out)
{
    const int row = blockIdx.x;
    const int tid = threadIdx.x;
    const float* xr = x    + (size_t)row*DD;
    const float* yr = ypre + (size_t)row*DD;
    float* outr     = out  + (size_t)row*DD;

    float vals[8];
    float s = 0.f, s2 = 0.f;
    #pragma unroll
    for (int k = 0; k < 8; ++k) {
        const int c = tid + k*256;
        const float v = yr[c];
        const float g = 0.5f*v*(1.f + erff(v*0.70710678118654752f));
        const float r = xr[c] + g;
        vals[k] = r;
        s += r; s2 += r*r;
    }

    // block reduce (8 warps)
    __shared__ float red[2][8];
    #pragma unroll
    for (int off = 16; off > 0; off >>= 1) {
        s  += __shfl_down_sync(0xFFFFFFFFu, s,  off);
        s2 += __shfl_down_sync(0xFFFFFFFFu, s2, off);
    }
    if ((tid & 31) == 0) { red[0][tid>>5] = s; red[1][tid>>5] = s2; }
    __syncthreads();
    float ts = 0.f, ts2 = 0.f;
    #pragma unroll
    for (int w = 0; w < 8; w++) { ts += red[0][w]; ts2 += red[1][w]; }

    const float mean = ts * (1.f/2048.f);
    const float var  = ts2 * (1.f/2048.f) - mean*mean;
    const float inv  = rsqrtf(var + 1e-5f);

    #pragma unroll
    for (int k = 0; k < 8; ++k) {
        const int c = tid + k*256;
        outr[c] = (vals[k] - mean)*inv*gamma[c] + beta[c];
    }
}

// ============================================================
// Launch
// ============================================================
extern "C" void kernel_launch(void* const* d_in, const int* in_sizes, int n_in,
                              void* d_out, int out_size)
{
    const float* x     = (const float*)d_in[0];
    const float* Wq    = (const float*)d_in[1];
    const float* bq    = (const float*)d_in[2];
    const float* Wk    = (const float*)d_in[3];
    const float* bk    = (const float*)d_in[4];
    const float* Wv    = (const float*)d_in[5];
    const float* bv    = (const float*)d_in[6];
    const float* Wo    = (const float*)d_in[7];
    const float* bo    = (const float*)d_in[8];
    const float* gamma = (const float*)d_in[9];
    const float* beta  = (const float*)d_in[10];
    float* out = (float*)d_out;

    float *Q, *K, *V, *CTX, *Y;
    cudaGetSymbolAddress((void**)&Q,   g_Q);
    cudaGetSymbolAddress((void**)&K,   g_K);
    cudaGetSymbolAddress((void**)&V,   g_V);
    cudaGetSymbolAddress((void**)&CTX, g_CTX);
    cudaGetSymbolAddress((void**)&Y,   g_Y);

    const dim3 blk(256);

    // QKV projections
    sgemm_bias<<<dim3(HE/128,  ML/128), blk>>>(x, Wq, bq, Q, ML, HE,  DD);
    sgemm_bias<<<dim3(KVE/128, ML/128), blk>>>(x, Wk, bk, K, ML, KVE, DD);
    sgemm_bias<<<dim3(KVE/128, ML/128), blk>>>(x, Wv, bv, V, ML, KVE, DD);

    // causal GQA flash attention
    const size_t fl_smem = (size_t)FL_SMEM_FLOATS * sizeof(float);
    cudaFuncSetAttribute(flash_kernel, cudaFuncAttributeMaxDynamicSharedMemorySize,
                         (int)fl_smem);
    flash_kernel<<<dim3(LL/64, BB*HH), blk, fl_smem>>>(Q, K, V, CTX);

    // output projection (pre-GELU)
    sgemm_bias<<<dim3(DD/128, ML/128), blk>>>(CTX, Wo, bo, Y, ML, DD, HE);

    // GELU + residual + LayerNorm
    epilogue_ln<<<ML, 256>>>(x, Y, gamma, beta, out);
}

// round 6
// speedup vs baseline: 3.6141x; 3.6141x over previous
#include <cuda_runtime.h>
#include <math.h>

// Problem constants
#define BB   2
#define LL   2048
#define DD   2048
#define HH   16
#define KVH  4
#define EE   128
#define ML   (BB*LL)        // 4096 rows total
#define HE   (HH*EE)        // 2048
#define KVE  (KVH*EE)       // 512

// -------- scratch (device globals; no allocation allowed) --------
__device__ float g_Q[ML*HE];      // [B*L, H*E]
__device__ float g_K[ML*KVE];     // [B*L, KV*E]
__device__ float g_V[ML*KVE];     // [B*L, KV*E]
__device__ float g_CTX[ML*HE];    // attention output (tf32-rounded)
__device__ float g_Y[ML*DD];      // pre-GELU O-proj output
// tf32-rounded (RNA) copies of GEMM operands
__device__ float g_xr[ML*DD];
__device__ float g_Wqr[DD*HE];
__device__ float g_Wkr[DD*KVE];
__device__ float g_Wvr[DD*KVE];
__device__ float g_Wor[HE*DD];

// ---------------- tf32 helpers ----------------
__device__ __forceinline__ float tf32r(float x) {
    float y;
    asm("cvt.rna.tf32.f32 %0, %1;" : "=f"(y) : "f"(x));
    return y;
}

// D += A@B  (m16n8k8 tf32)
__device__ __forceinline__ void mma8(float* d, const unsigned* a, const unsigned* b) {
    asm volatile(
        "mma.sync.aligned.m16n8k8.row.col.f32.tf32.tf32.f32 "
        "{%0,%1,%2,%3}, {%4,%5,%6,%7}, {%8,%9}, {%0,%1,%2,%3};\n"
        : "+f"(d[0]), "+f"(d[1]), "+f"(d[2]), "+f"(d[3])
        : "r"(a[0]), "r"(a[1]), "r"(a[2]), "r"(a[3]),
          "r"(b[0]), "r"(b[1]));
}

__device__ __forceinline__ void cp16(void* smem_dst, const void* gmem_src) {
    unsigned s = (unsigned)__cvta_generic_to_shared(smem_dst);
    asm volatile("cp.async.cg.shared.global [%0], [%1], 16;\n" :: "r"(s), "l"(gmem_src));
}

// ============================================================
// Pre-round: out[i] = round_to_tf32(in[i])  (RNA)
// ============================================================
__global__ __launch_bounds__(256)
void round_tf32_k(const float4* __restrict__ in, float4* __restrict__ out, int n4)
{
    int i = blockIdx.x * 256 + threadIdx.x;
    if (i < n4) {
        float4 v = in[i];
        v.x = tf32r(v.x); v.y = tf32r(v.y); v.z = tf32r(v.z); v.w = tf32r(v.w);
        out[i] = v;
    }
}

// ============================================================
// tf32 tensor-core GEMM: C[M,N] = A[M,K] @ B[K,N] + bias[N]
// A,B already tf32-rounded. 128x128 tile, BK=16, cp.async double buffer.
// 256 threads = 8 warps, warp tile 64x32 (4 m-tiles x 4 n-tiles of m16n8).
// Requires M%128==0, N%128==0, K%16==0.
// ============================================================
#define GBK 16

__global__ __launch_bounds__(256)
void gemm_tf32(const float* __restrict__ A, const float* __restrict__ B,
               const float* __restrict__ bias, float* __restrict__ C,
               int M, int N, int K)
{
    __shared__ float As[2][128][20];    // pad 20: conflict-free A frags
    __shared__ float Bs[2][16][136];    // pad 136: conflict-free B frags

    const int tid  = threadIdx.x;
    const int w    = tid >> 5, lane = tid & 31;
    const int lg   = lane >> 2, lt = lane & 3;
    const int wm   = w & 1,  wn = w >> 1;        // 2x4 warp grid
    const int bx   = blockIdx.x, by = blockIdx.y;

    const float* Ag = A + (size_t)(by * 128) * K;
    const float* Bg = B + (size_t)bx * 128;

    float acc[4][4][4];
    #pragma unroll
    for (int mt = 0; mt < 4; mt++)
        #pragma unroll
        for (int nt = 0; nt < 4; nt++)
            #pragma unroll
            for (int f = 0; f < 4; f++) acc[mt][nt][f] = 0.f;

    auto issue = [&](int buf, int k0) {
        // A tile 128x16: 512 16B-chunks, 2 per thread
        #pragma unroll
        for (int i = 0; i < 2; i++) {
            int q = tid + i * 256;
            int r = q >> 2, c4 = (q & 3) * 4;
            cp16(&As[buf][r][c4], Ag + (size_t)r * K + k0 + c4);
        }
        // B tile 16x128: 512 chunks
        #pragma unroll
        for (int i = 0; i < 2; i++) {
            int q = tid + i * 256;
            int r = q >> 5, c = (q & 31) * 4;
            cp16(&Bs[buf][r][c], Bg + (size_t)(k0 + r) * N + c);
        }
        asm volatile("cp.async.commit_group;\n");
    };

    issue(0, 0);
    const int KT = K / GBK;

    for (int kt = 0; kt < KT; ++kt) {
        asm volatile("cp.async.wait_group 0;\n");
        __syncthreads();
        if (kt + 1 < KT) issue((kt + 1) & 1, (kt + 1) * GBK);
        const int buf = kt & 1;

        #pragma unroll
        for (int k8 = 0; k8 < GBK; k8 += 8) {
            unsigned af[4][4];
            #pragma unroll
            for (int mt = 0; mt < 4; mt++) {
                int r = wm * 64 + mt * 16 + lg;
                af[mt][0] = __float_as_uint(As[buf][r    ][k8 + lt    ]);
                af[mt][1] = __float_as_uint(As[buf][r + 8][k8 + lt    ]);
                af[mt][2] = __float_as_uint(As[buf][r    ][k8 + lt + 4]);
                af[mt][3] = __float_as_uint(As[buf][r + 8][k8 + lt + 4]);
            }
            unsigned bf[4][2];
            #pragma unroll
            for (int nt = 0; nt < 4; nt++) {
                int c = wn * 32 + nt * 8 + lg;
                bf[nt][0] = __float_as_uint(Bs[buf][k8 + lt    ][c]);
                bf[nt][1] = __float_as_uint(Bs[buf][k8 + lt + 4][c]);
            }
            #pragma unroll
            for (int mt = 0; mt < 4; mt++)
                #pragma unroll
                for (int nt = 0; nt < 4; nt++)
                    mma8(acc[mt][nt], af[mt], bf[nt]);
        }
    }

    // epilogue: bias add + store
    #pragma unroll
    for (int mt = 0; mt < 4; mt++) {
        const int r0 = by * 128 + wm * 64 + mt * 16 + lg;
        #pragma unroll
        for (int nt = 0; nt < 4; nt++) {
            const int c = bx * 128 + wn * 32 + nt * 8 + lt * 2;
            const float b0 = bias[c], b1 = bias[c + 1];
            float2 o0, o1;
            o0.x = acc[mt][nt][0] + b0;  o0.y = acc[mt][nt][1] + b1;
            o1.x = acc[mt][nt][2] + b0;  o1.y = acc[mt][nt][3] + b1;
            *(float2*)(C + (size_t)r0      * N + c) = o0;
            *(float2*)(C + (size_t)(r0 + 8) * N + c) = o1;
        }
    }
}

// ============================================================
// Flash attention (causal, GQA) with tf32 mma.sync.
// Block: 128 query rows (two 64-row halves), Bc=64 keys/tile, E=128.
// 8 warps x 16 query rows. Online softmax in registers.
// ============================================================
#define FQ_PAD 132
#define FK_PAD 132
#define FV_PAD 136
#define FP_PAD 68
// floats: Qs 128*132 + Ks 64*132 + Vs 64*136 + Ps 8*16*68
#define FL2_SMEM_FLOATS (128*FQ_PAD + 64*FK_PAD + 64*FV_PAD + 8*16*FP_PAD)

__global__ __launch_bounds__(256)
void flash_tf32(const float* __restrict__ Q, const float* __restrict__ K,
                const float* __restrict__ V, float* __restrict__ ctx)
{
    extern __shared__ float sm[];
    float* Qs = sm;                        // [128][132] tf32-rounded, pre-scaled
    float* Ks = Qs + 128 * FQ_PAD;         // [64][132]
    float* Vs = Ks + 64 * FK_PAD;          // [64][136]
    float* Ps = Vs + 64 * FV_PAD;          // [8][16][68] per-warp P

    const int tid  = threadIdx.x;
    const int w    = tid >> 5, lane = tid & 31;
    const int lg   = lane >> 2, lt = lane & 3;
    const int h2   = w >> 2, wq = w & 3;       // half, warp-in-half
    const int bh   = blockIdx.y;
    const int b    = bh / HH, h = bh % HH, kvh = h % KVH;
    const int qb   = blockIdx.x * 128;
    const int qrl  = h2 * 64 + wq * 16;        // warp's local q-row base
    const int qr0  = qb + qrl;                 // global q-row base
    const float scale = 0.08838834764831845f;  // 1/sqrt(128)

    // ---- load Q tile (scaled + tf32-rounded) ----
    {
        const float* Qg = Q + ((size_t)(b * LL + qb)) * HE + h * EE;
        #pragma unroll
        for (int i = 0; i < 16; i++) {
            int q = tid + i * 256;             // 4096 chunks
            int r = q >> 5, c4 = (q & 31) * 4;
            float4 v = *(const float4*)(Qg + (size_t)r * HE + c4);
            v.x = tf32r(v.x * scale); v.y = tf32r(v.y * scale);
            v.z = tf32r(v.z * scale); v.w = tf32r(v.w * scale);
            *(float4*)(Qs + r * FQ_PAD + c4) = v;
        }
    }

    float O[16][4];
    #pragma unroll
    for (int n = 0; n < 16; n++)
        #pragma unroll
        for (int f = 0; f < 4; f++) O[n][f] = 0.f;
    float m0 = -INFINITY, m1 = -INFINITY, l0 = 0.f, l1 = 0.f;

    const int ntiles = (qb >> 6) + 2;
    for (int t = 0; t < ntiles; ++t) {
        const int kb = t * 64;
        __syncthreads();   // protect Qs (1st iter) + Ks/Vs reuse

        // ---- cooperative K/V tile load (tf32-rounded) ----
        {
            const float* Kg = K + ((size_t)(b * LL + kb)) * KVE + kvh * EE;
            const float* Vg = V + ((size_t)(b * LL + kb)) * KVE + kvh * EE;
            #pragma unroll
            for (int i = 0; i < 8; i++) {
                int q = tid + i * 256;         // 2048 chunks each
                int r = q >> 5, c4 = (q & 31) * 4;
                float4 vk = *(const float4*)(Kg + (size_t)r * KVE + c4);
                vk.x = tf32r(vk.x); vk.y = tf32r(vk.y);
                vk.z = tf32r(vk.z); vk.w = tf32r(vk.w);
                *(float4*)(Ks + r * FK_PAD + c4) = vk;
                float4 vv = *(const float4*)(Vg + (size_t)r * KVE + c4);
                vv.x = tf32r(vv.x); vv.y = tf32r(vv.y);
                vv.z = tf32r(vv.z); vv.w = tf32r(vv.w);
                *(float4*)(Vs + r * FV_PAD + c4) = vv;
            }
        }
        __syncthreads();

        if (kb <= qr0 + 15) {   // tile not fully above warp's rows
            // ---- S = Q @ K^T  (warp strip 16x64) ----
            float s[8][4];
            #pragma unroll
            for (int nn = 0; nn < 8; nn++)
                #pragma unroll
                for (int f = 0; f < 4; f++) s[nn][f] = 0.f;

            #pragma unroll
            for (int e8 = 0; e8 < EE; e8 += 8) {
                unsigned af[4];
                af[0] = __float_as_uint(Qs[(qrl + lg    ) * FQ_PAD + e8 + lt    ]);
                af[1] = __float_as_uint(Qs[(qrl + lg + 8) * FQ_PAD + e8 + lt    ]);
                af[2] = __float_as_uint(Qs[(qrl + lg    ) * FQ_PAD + e8 + lt + 4]);
                af[3] = __float_as_uint(Qs[(qrl + lg + 8) * FQ_PAD + e8 + lt + 4]);
                #pragma unroll
                for (int nn = 0; nn < 8; nn++) {
                    unsigned bf[2];
                    bf[0] = __float_as_uint(Ks[(nn * 8 + lg) * FK_PAD + e8 + lt    ]);
                    bf[1] = __float_as_uint(Ks[(nn * 8 + lg) * FK_PAD + e8 + lt + 4]);
                    mma8(s[nn], af, bf);
                }
            }

            // ---- causal mask (only the warp's diagonal tile) ----
            if (kb + 63 > qr0) {
                const int r0g = qr0 + lg, r1g = qr0 + lg + 8;
                #pragma unroll
                for (int nn = 0; nn < 8; nn++) {
                    const int c0 = kb + nn * 8 + lt * 2;
                    if (c0     > r0g) s[nn][0] = -1e30f;
                    if (c0 + 1 > r0g) s[nn][1] = -1e30f;
                    if (c0     > r1g) s[nn][2] = -1e30f;
                    if (c0 + 1 > r1g) s[nn][3] = -1e30f;
                }
            }

            // ---- online softmax (rows lg and lg+8) ----
            float mx0 = -1e30f, mx1 = -1e30f;
            #pragma unroll
            for (int nn = 0; nn < 8; nn++) {
                mx0 = fmaxf(mx0, fmaxf(s[nn][0], s[nn][1]));
                mx1 = fmaxf(mx1, fmaxf(s[nn][2], s[nn][3]));
            }
            mx0 = fmaxf(mx0, __shfl_xor_sync(0xFFFFFFFFu, mx0, 1));
            mx0 = fmaxf(mx0, __shfl_xor_sync(0xFFFFFFFFu, mx0, 2));
            mx1 = fmaxf(mx1, __shfl_xor_sync(0xFFFFFFFFu, mx1, 1));
            mx1 = fmaxf(mx1, __shfl_xor_sync(0xFFFFFFFFu, mx1, 2));

            const float mn0 = fmaxf(m0, mx0), mn1 = fmaxf(m1, mx1);
            const float a0 = __expf(m0 - mn0), a1 = __expf(m1 - mn1);
            float rs0 = 0.f, rs1 = 0.f;
            #pragma unroll
            for (int nn = 0; nn < 8; nn++) {
                float p0 = __expf(s[nn][0] - mn0);
                float p1 = __expf(s[nn][1] - mn0);
                float p2 = __expf(s[nn][2] - mn1);
                float p3 = __expf(s[nn][3] - mn1);
                s[nn][0] = p0; s[nn][1] = p1; s[nn][2] = p2; s[nn][3] = p3;
                rs0 += p0 + p1; rs1 += p2 + p3;
            }
            rs0 += __shfl_xor_sync(0xFFFFFFFFu, rs0, 1);
            rs0 += __shfl_xor_sync(0xFFFFFFFFu, rs0, 2);
            rs1 += __shfl_xor_sync(0xFFFFFFFFu, rs1, 1);
            rs1 += __shfl_xor_sync(0xFFFFFFFFu, rs1, 2);

            m0 = mn0; m1 = mn1;
            l0 = l0 * a0 + rs0;
            l1 = l1 * a1 + rs1;

            // rescale O
            #pragma unroll
            for (int n = 0; n < 16; n++) {
                O[n][0] *= a0; O[n][1] *= a0;
                O[n][2] *= a1; O[n][3] *= a1;
            }

            // ---- P -> smem (C-layout to A-layout via per-warp buffer) ----
            float* Pw = Ps + w * 16 * FP_PAD;
            #pragma unroll
            for (int nn = 0; nn < 8; nn++) {
                float2 p0, p1;
                p0.x = tf32r(s[nn][0]); p0.y = tf32r(s[nn][1]);
                p1.x = tf32r(s[nn][2]); p1.y = tf32r(s[nn][3]);
                *(float2*)(Pw + lg       * FP_PAD + nn * 8 + lt * 2) = p0;
                *(float2*)(Pw + (lg + 8) * FP_PAD + nn * 8 + lt * 2) = p1;
            }
            __syncwarp();

            // ---- O += P @ V ----
            #pragma unroll
            for (int kk = 0; kk < 64; kk += 8) {
                unsigned af[4];
                af[0] = __float_as_uint(Pw[ lg      * FP_PAD + kk + lt    ]);
                af[1] = __float_as_uint(Pw[(lg + 8) * FP_PAD + kk + lt    ]);
                af[2] = __float_as_uint(Pw[ lg      * FP_PAD + kk + lt + 4]);
                af[3] = __float_as_uint(Pw[(lg + 8) * FP_PAD + kk + lt + 4]);
                #pragma unroll
                for (int n = 0; n < 16; n++) {
                    unsigned bf[2];
                    bf[0] = __float_as_uint(Vs[(kk + lt    ) * FV_PAD + n * 8 + lg]);
                    bf[1] = __float_as_uint(Vs[(kk + lt + 4) * FV_PAD + n * 8 + lg]);
                    mma8(O[n], af, bf);
                }
            }
        }
    }

    // ---- write ctx (normalized, tf32-rounded for the O-proj GEMM) ----
    const float inv0 = 1.f / l0, inv1 = 1.f / l1;
    float* Cg = ctx + ((size_t)(b * LL + qr0)) * HE + h * EE;
    #pragma unroll
    for (int n = 0; n < 16; n++) {
        const int c = n * 8 + lt * 2;
        float2 o0, o1;
        o0.x = tf32r(O[n][0] * inv0); o0.y = tf32r(O[n][1] * inv0);
        o1.x = tf32r(O[n][2] * inv1); o1.y = tf32r(O[n][3] * inv1);
        *(float2*)(Cg + (size_t)lg       * HE + c) = o0;
        *(float2*)(Cg + (size_t)(lg + 8) * HE + c) = o1;
    }
}

// ============================================================
// Epilogue: out = LayerNorm(x + gelu_erf(ypre)) * gamma + beta
// ============================================================
__global__ __launch_bounds__(256)
void epilogue_ln(const float* __restrict__ x, const float* __restrict__ ypre,
                 const float* __restrict__ gamma, const float* __restrict__ beta,
                 float* __restrict__ out)
{
    const int row = blockIdx.x;
    const int tid = threadIdx.x;
    const float* xr = x    + (size_t)row*DD;
    const float* yr = ypre + (size_t)row*DD;
    float* outr     = out  + (size_t)row*DD;

    float vals[8];
    float s = 0.f, s2 = 0.f;
    #pragma unroll
    for (int k = 0; k < 8; ++k) {
        const int c = tid + k*256;
        const float v = yr[c];
        const float g = 0.5f*v*(1.f + erff(v*0.70710678118654752f));
        const float r = xr[c] + g;
        vals[k] = r;
        s += r; s2 += r*r;
    }

    __shared__ float red[2][8];
    #pragma unroll
    for (int off = 16; off > 0; off >>= 1) {
        s  += __shfl_down_sync(0xFFFFFFFFu, s,  off);
        s2 += __shfl_down_sync(0xFFFFFFFFu, s2, off);
    }
    if ((tid & 31) == 0) { red[0][tid>>5] = s; red[1][tid>>5] = s2; }
    __syncthreads();
    float ts = 0.f, ts2 = 0.f;
    #pragma unroll
    for (int w = 0; w < 8; w++) { ts += red[0][w]; ts2 += red[1][w]; }

    const float mean = ts * (1.f/2048.f);
    const float var  = ts2 * (1.f/2048.f) - mean*mean;
    const float inv  = rsqrtf(var + 1e-5f);

    #pragma unroll
    for (int k = 0; k < 8; ++k) {
        const int c = tid + k*256;
        outr[c] = (vals[k] - mean)*inv*gamma[c] + beta[c];
    }
}

// ============================================================
// Launch
// ============================================================
extern "C" void kernel_launch(void* const* d_in, const int* in_sizes, int n_in,
                              void* d_out, int out_size)
{
    const float* x     = (const float*)d_in[0];
    const float* Wq    = (const float*)d_in[1];
    const float* bq    = (const float*)d_in[2];
    const float* Wk    = (const float*)d_in[3];
    const float* bk    = (const float*)d_in[4];
    const float* Wv    = (const float*)d_in[5];
    const float* bv    = (const float*)d_in[6];
    const float* Wo    = (const float*)d_in[7];
    const float* bo    = (const float*)d_in[8];
    const float* gamma = (const float*)d_in[9];
    const float* beta  = (const float*)d_in[10];
    float* out = (float*)d_out;

    float *Q, *K, *V, *CTX, *Y, *xr, *Wqr, *Wkr, *Wvr, *Wor;
    cudaGetSymbolAddress((void**)&Q,   g_Q);
    cudaGetSymbolAddress((void**)&K,   g_K);
    cudaGetSymbolAddress((void**)&V,   g_V);
    cudaGetSymbolAddress((void**)&CTX, g_CTX);
    cudaGetSymbolAddress((void**)&Y,   g_Y);
    cudaGetSymbolAddress((void**)&xr,  g_xr);
    cudaGetSymbolAddress((void**)&Wqr, g_Wqr);
    cudaGetSymbolAddress((void**)&Wkr, g_Wkr);
    cudaGetSymbolAddress((void**)&Wvr, g_Wvr);
    cudaGetSymbolAddress((void**)&Wor, g_Wor);

    const dim3 blk(256);

    // pre-round GEMM operands to tf32 (RNA) -> kills HMMA truncation bias
    round_tf32_k<<<(ML*DD/4 + 255)/256, blk>>>((const float4*)x,  (float4*)xr,  ML*DD/4);
    round_tf32_k<<<(DD*HE/4 + 255)/256, blk>>>((const float4*)Wq, (float4*)Wqr, DD*HE/4);
    round_tf32_k<<<(DD*KVE/4 + 255)/256, blk>>>((const float4*)Wk, (float4*)Wkr, DD*KVE/4);
    round_tf32_k<<<(DD*KVE/4 + 255)/256, blk>>>((const float4*)Wv, (float4*)Wvr, DD*KVE/4);
    round_tf32_k<<<(HE*DD/4 + 255)/256, blk>>>((const float4*)Wo, (float4*)Wor, HE*DD/4);

    // QKV projections (tensor-core tf32)
    gemm_tf32<<<dim3(HE/128,  ML/128), blk>>>(xr, Wqr, bq, Q, ML, HE,  DD);
    gemm_tf32<<<dim3(KVE/128, ML/128), blk>>>(xr, Wkr, bk, K, ML, KVE, DD);
    gemm_tf32<<<dim3(KVE/128, ML/128), blk>>>(xr, Wvr, bv, V, ML, KVE, DD);

    // causal GQA flash attention (tensor-core tf32)
    const size_t fl_smem = (size_t)FL2_SMEM_FLOATS * sizeof(float);
    cudaFuncSetAttribute(flash_tf32, cudaFuncAttributeMaxDynamicSharedMemorySize,
                         (int)fl_smem);
    flash_tf32<<<dim3(LL/128, BB*HH), blk, fl_smem>>>(Q, K, V, CTX);

    // output projection (pre-GELU)
    gemm_tf32<<<dim3(DD/128, ML/128), blk>>>(CTX, Wor, bo, Y, ML, DD, HE);

    // GELU + residual + LayerNorm
    epilogue_ln<<<ML, 256>>>(x, Y, gamma, beta, out);
}

// round 7
// speedup vs baseline: 6.1825x; 1.7106x over previous
#include <cuda_runtime.h>
#include <cuda_bf16.h>
#include <math.h>

// Problem constants
#define BB   2
#define LL   2048
#define DD   2048
#define HH   16
#define KVH  4
#define EE   128
#define ML   (BB*LL)        // 4096 rows total
#define HE   (HH*EE)        // 2048
#define KVE  (KVH*EE)       // 512
#define KVN  1024           // fused K|V projection width

// -------- scratch (device globals; no allocation allowed) --------
__device__ __nv_bfloat16 g_xb[ML*DD];        // x in bf16
__device__ __nv_bfloat16 g_Wqt[HE*DD];       // Wq^T  [N=2048][K=2048] bf16
__device__ __nv_bfloat16 g_Wkvt[KVN*DD];     // [Wk|Wv]^T [N=1024][K=2048] bf16
__device__ __nv_bfloat16 g_Wot[DD*HE];       // Wo^T  [N=2048][K=2048] bf16
__device__ float         g_bkv[KVN];         // bk|bv concatenated
__device__ __nv_bfloat16 g_Qb[ML*HE];        // Q bf16
__device__ __nv_bfloat16 g_KVb[ML*KVN];      // K|V bf16, row stride 1024
__device__ __nv_bfloat16 g_CTXb[ML*HE];      // attention output bf16
__device__ float         g_Y[ML*DD];         // pre-GELU O-proj output fp32

// ---------------- helpers ----------------
// D += A@B  (m16n8k16 bf16, fp32 accumulate)
__device__ __forceinline__ void mma16(float* d, const unsigned* a, const unsigned* b) {
    asm volatile(
        "mma.sync.aligned.m16n8k16.row.col.f32.bf16.bf16.f32 "
        "{%0,%1,%2,%3}, {%4,%5,%6,%7}, {%8,%9}, {%0,%1,%2,%3};\n"
        : "+f"(d[0]), "+f"(d[1]), "+f"(d[2]), "+f"(d[3])
        : "r"(a[0]), "r"(a[1]), "r"(a[2]), "r"(a[3]),
          "r"(b[0]), "r"(b[1]));
}

__device__ __forceinline__ void cp16(void* smem_dst, const void* gmem_src) {
    unsigned s = (unsigned)__cvta_generic_to_shared(smem_dst);
    asm volatile("cp.async.cg.shared.global [%0], [%1], 16;\n" :: "r"(s), "l"(gmem_src));
}

__device__ __forceinline__ unsigned bf2pack(float x, float y) {
    __nv_bfloat162 v = __float22bfloat162_rn(make_float2(x, y));
    return *(unsigned*)&v;
}

// ============================================================
// x: fp32 -> bf16 (elementwise)
// ============================================================
__global__ __launch_bounds__(256)
void f32_to_bf16_k(const float4* __restrict__ in, uint2* __restrict__ out, int n4)
{
    int i = blockIdx.x * 256 + threadIdx.x;
    if (i < n4) {
        float4 v = in[i];
        uint2 o;
        o.x = bf2pack(v.x, v.y);
        o.y = bf2pack(v.z, v.w);
        out[i] = o;
    }
}

// ============================================================
// W[Kd][Nd] fp32 -> Wt[Nd][Kd] bf16 (tiled transpose)
// ============================================================
__global__ __launch_bounds__(256)
void transpose_bf16_k(const float* __restrict__ W, __nv_bfloat16* __restrict__ Wt,
                      int Kd, int Nd)
{
    __shared__ float t[32][33];
    const int n0 = blockIdx.x * 32, k0 = blockIdx.y * 32;
    const int tx = threadIdx.x & 31, ty = threadIdx.x >> 5;   // ty 0..7
    #pragma unroll
    for (int i = 0; i < 4; i++)
        t[ty + 8*i][tx] = W[(size_t)(k0 + ty + 8*i) * Nd + n0 + tx];
    __syncthreads();
    #pragma unroll
    for (int i = 0; i < 4; i++)
        Wt[(size_t)(n0 + ty + 8*i) * Kd + k0 + tx] = __float2bfloat16(t[tx][ty + 8*i]);
}

__global__ void concat_bias_k(const float* __restrict__ bk, const float* __restrict__ bv,
                              float* __restrict__ bkv)
{
    int i = blockIdx.x * 256 + threadIdx.x;
    if (i < 512)            bkv[i] = bk[i];
    else if (i < 1024)      bkv[i] = bv[i - 512];
}

// ============================================================
// bf16 tensor-core GEMM: C[M,N] = A[M,K] @ W[K,N] + bias[N]
// A bf16 [M][K] row-major; Bt = W^T bf16 [N][K] row-major.
// 128x128 tile, BK=32, cp.async double buffer, 8 warps (64x32 warp tile).
// OUT_BF16: store bf16, else fp32. Requires M,N%128==0, K%32==0.
// ============================================================
#define GBK 32

template<bool OUT_BF16>
__global__ __launch_bounds__(256)
void gemm_bf16(const __nv_bfloat16* __restrict__ A, const __nv_bfloat16* __restrict__ Bt,
               const float* __restrict__ bias, void* __restrict__ Cout,
               int M, int N, int K, int ldc)
{
    __shared__ __nv_bfloat16 As[2][128][40];   // [m][k], pad 40
    __shared__ __nv_bfloat16 Bs[2][128][40];   // [n][k], pad 40

    const int tid  = threadIdx.x;
    const int w    = tid >> 5, lane = tid & 31;
    const int lg   = lane >> 2, lt = lane & 3;
    const int wm   = w & 1, wn = w >> 1;        // 2x4 warp grid
    const int bx   = blockIdx.x, by = blockIdx.y;

    const __nv_bfloat16* Ag = A  + (size_t)(by * 128) * K;
    const __nv_bfloat16* Bg = Bt + (size_t)(bx * 128) * K;

    float acc[4][4][4];
    #pragma unroll
    for (int mt = 0; mt < 4; mt++)
        #pragma unroll
        for (int nt = 0; nt < 4; nt++)
            #pragma unroll
            for (int f = 0; f < 4; f++) acc[mt][nt][f] = 0.f;

    auto issue = [&](int buf, int k0) {
        #pragma unroll
        for (int i = 0; i < 2; i++) {          // A tile 128x32 halves: 512 16B chunks
            int q = tid + i * 256;
            int r = q >> 2, c8 = (q & 3) * 8;
            cp16(&As[buf][r][c8], Ag + (size_t)r * K + k0 + c8);
        }
        #pragma unroll
        for (int i = 0; i < 2; i++) {          // B tile 128x32 halves
            int q = tid + i * 256;
            int r = q >> 2, c8 = (q & 3) * 8;
            cp16(&Bs[buf][r][c8], Bg + (size_t)r * K + k0 + c8);
        }
        asm volatile("cp.async.commit_group;\n");
    };

    issue(0, 0);
    const int KT = K / GBK;

    for (int kt = 0; kt < KT; ++kt) {
        asm volatile("cp.async.wait_group 0;\n");
        __syncthreads();
        if (kt + 1 < KT) issue((kt + 1) & 1, (kt + 1) * GBK);
        const int buf = kt & 1;

        #pragma unroll
        for (int k8 = 0; k8 < GBK; k8 += 16) {
            unsigned af[4][4];
            #pragma unroll
            for (int mt = 0; mt < 4; mt++) {
                int r = wm * 64 + mt * 16 + lg;
                af[mt][0] = *(const unsigned*)&As[buf][r    ][k8 + lt*2    ];
                af[mt][1] = *(const unsigned*)&As[buf][r + 8][k8 + lt*2    ];
                af[mt][2] = *(const unsigned*)&As[buf][r    ][k8 + lt*2 + 8];
                af[mt][3] = *(const unsigned*)&As[buf][r + 8][k8 + lt*2 + 8];
            }
            unsigned bf2[4][2];
            #pragma unroll
            for (int nt = 0; nt < 4; nt++) {
                int c = wn * 32 + nt * 8 + lg;
                bf2[nt][0] = *(const unsigned*)&Bs[buf][c][k8 + lt*2    ];
                bf2[nt][1] = *(const unsigned*)&Bs[buf][c][k8 + lt*2 + 8];
            }
            #pragma unroll
            for (int mt = 0; mt < 4; mt++)
                #pragma unroll
                for (int nt = 0; nt < 4; nt++)
                    mma16(acc[mt][nt], af[mt], bf2[nt]);
        }
    }

    // epilogue: bias + store
    #pragma unroll
    for (int mt = 0; mt < 4; mt++) {
        const int r0 = by * 128 + wm * 64 + mt * 16 + lg;
        #pragma unroll
        for (int nt = 0; nt < 4; nt++) {
            const int c = bx * 128 + wn * 32 + nt * 8 + lt * 2;
            const float b0 = bias[c], b1 = bias[c + 1];
            if (OUT_BF16) {
                __nv_bfloat16* Cb = (__nv_bfloat16*)Cout;
                unsigned o0 = bf2pack(acc[mt][nt][0] + b0, acc[mt][nt][1] + b1);
                unsigned o1 = bf2pack(acc[mt][nt][2] + b0, acc[mt][nt][3] + b1);
                *(unsigned*)(Cb + (size_t)r0       * ldc + c) = o0;
                *(unsigned*)(Cb + (size_t)(r0 + 8) * ldc + c) = o1;
            } else {
                float* Cf = (float*)Cout;
                float2 o0, o1;
                o0.x = acc[mt][nt][0] + b0;  o0.y = acc[mt][nt][1] + b1;
                o1.x = acc[mt][nt][2] + b0;  o1.y = acc[mt][nt][3] + b1;
                *(float2*)(Cf + (size_t)r0       * ldc + c) = o0;
                *(float2*)(Cf + (size_t)(r0 + 8) * ldc + c) = o1;
            }
        }
    }
}

// ============================================================
// Flash attention (causal, GQA), bf16 mma.sync m16n8k16.
// Block: 128 q-rows, Bc=64 keys/tile, E=128. 8 warps x 16 q-rows.
// ============================================================
#define FQP 136   // Qs/Ks row pad (halves)
#define FVP 72    // Vst/Ps row pad (halves)
// halves: Qs 128*136 + Ks 64*136 + Vst 128*72 + Ps 8*16*72
#define FL_SMEM_HALVES (128*FQP + 64*FQP + 128*FVP + 8*16*FVP)

__global__ __launch_bounds__(256)
void flash_bf16(const __nv_bfloat16* __restrict__ Qg_, const __nv_bfloat16* __restrict__ KVg_,
                __nv_bfloat16* __restrict__ ctx)
{
    extern __shared__ __nv_bfloat16 sm[];
    __nv_bfloat16* Qs  = sm;                   // [128][136]
    __nv_bfloat16* Ks  = Qs  + 128 * FQP;      // [64][136]
    __nv_bfloat16* Vst = Ks  + 64 * FQP;       // [128 e][72 keys] (V transposed)
    __nv_bfloat16* Ps  = Vst + 128 * FVP;      // [8 warps][16][72]

    const int tid  = threadIdx.x;
    const int w    = tid >> 5, lane = tid & 31;
    const int lg   = lane >> 2, lt = lane & 3;
    const int h2   = w >> 2, wq = w & 3;
    const int bh   = blockIdx.y;
    const int b    = bh / HH, h = bh % HH, kvh = h % KVH;
    const int qb   = blockIdx.x * 128;
    const int qrl  = h2 * 64 + wq * 16;
    const int qr0  = qb + qrl;
    const float scale = 0.08838834764831845f;   // 1/sqrt(128)

    // ---- Q tile (bf16 copy) ----
    {
        const __nv_bfloat16* Qg = Qg_ + ((size_t)(b * LL + qb)) * HE + h * EE;
        #pragma unroll
        for (int i = 0; i < 8; i++) {
            int q = tid + i * 256;             // 2048 16B chunks
            int r = q >> 4, c8 = (q & 15) * 8;
            *(uint4*)&Qs[r * FQP + c8] = *(const uint4*)(Qg + (size_t)r * HE + c8);
        }
    }

    float O[16][4];
    #pragma unroll
    for (int n = 0; n < 16; n++)
        #pragma unroll
        for (int f = 0; f < 4; f++) O[n][f] = 0.f;
    float m0 = -INFINITY, m1 = -INFINITY, l0 = 0.f, l1 = 0.f;

    const int ntiles = (qb >> 6) + 2;
    for (int t = 0; t < ntiles; ++t) {
        const int kb = t * 64;
        __syncthreads();   // protect Qs (1st iter) + Ks/Vst reuse

        const __nv_bfloat16* Kg = KVg_ + ((size_t)(b * LL + kb)) * KVN + kvh * EE;
        const __nv_bfloat16* Vg = Kg + KVE;   // V at +512 within fused row
        // K: row-major copy (64 x 128 halves = 1024 chunks)
        #pragma unroll
        for (int i = 0; i < 4; i++) {
            int q = tid + i * 256;
            int r = q >> 4, c8 = (q & 15) * 8;
            *(uint4*)&Ks[r * FQP + c8] = *(const uint4*)(Kg + (size_t)r * KVN + c8);
        }
        // V: transpose into Vst[e][key]; lane-major keys -> conflict-free STS.16
        #pragma unroll
        for (int i = 0; i < 4; i++) {
            int q = tid + i * 256;
            int r = q & 63, c8 = (q >> 6) * 8;
            uint4 u = *(const uint4*)(Vg + (size_t)r * KVN + c8);
            __nv_bfloat16 e[8];
            *(uint4*)e = u;
            #pragma unroll
            for (int j = 0; j < 8; j++) Vst[(c8 + j) * FVP + r] = e[j];
        }
        __syncthreads();

        if (kb <= qr0 + 15) {
            // ---- S = Q @ K^T (warp strip 16x64) ----
            float s[8][4];
            #pragma unroll
            for (int nn = 0; nn < 8; nn++)
                #pragma unroll
                for (int f = 0; f < 4; f++) s[nn][f] = 0.f;

            #pragma unroll
            for (int e8 = 0; e8 < EE; e8 += 16) {
                unsigned af[4];
                af[0] = *(const unsigned*)&Qs[(qrl + lg    ) * FQP + e8 + lt*2    ];
                af[1] = *(const unsigned*)&Qs[(qrl + lg + 8) * FQP + e8 + lt*2    ];
                af[2] = *(const unsigned*)&Qs[(qrl + lg    ) * FQP + e8 + lt*2 + 8];
                af[3] = *(const unsigned*)&Qs[(qrl + lg + 8) * FQP + e8 + lt*2 + 8];
                #pragma unroll
                for (int nn = 0; nn < 8; nn++) {
                    unsigned bf2r[2];
                    bf2r[0] = *(const unsigned*)&Ks[(nn*8 + lg) * FQP + e8 + lt*2    ];
                    bf2r[1] = *(const unsigned*)&Ks[(nn*8 + lg) * FQP + e8 + lt*2 + 8];
                    mma16(s[nn], af, bf2r);
                }
            }
            // scale in fp32
            #pragma unroll
            for (int nn = 0; nn < 8; nn++)
                #pragma unroll
                for (int f = 0; f < 4; f++) s[nn][f] *= scale;

            // ---- causal mask (diagonal tile only) ----
            if (kb + 63 > qr0) {
                const int r0g = qr0 + lg, r1g = qr0 + lg + 8;
                #pragma unroll
                for (int nn = 0; nn < 8; nn++) {
                    const int c0 = kb + nn * 8 + lt * 2;
                    if (c0     > r0g) s[nn][0] = -1e30f;
                    if (c0 + 1 > r0g) s[nn][1] = -1e30f;
                    if (c0     > r1g) s[nn][2] = -1e30f;
                    if (c0 + 1 > r1g) s[nn][3] = -1e30f;
                }
            }

            // ---- online softmax (rows lg, lg+8) ----
            float mx0 = -1e30f, mx1 = -1e30f;
            #pragma unroll
            for (int nn = 0; nn < 8; nn++) {
                mx0 = fmaxf(mx0, fmaxf(s[nn][0], s[nn][1]));
                mx1 = fmaxf(mx1, fmaxf(s[nn][2], s[nn][3]));
            }
            mx0 = fmaxf(mx0, __shfl_xor_sync(0xFFFFFFFFu, mx0, 1));
            mx0 = fmaxf(mx0, __shfl_xor_sync(0xFFFFFFFFu, mx0, 2));
            mx1 = fmaxf(mx1, __shfl_xor_sync(0xFFFFFFFFu, mx1, 1));
            mx1 = fmaxf(mx1, __shfl_xor_sync(0xFFFFFFFFu, mx1, 2));

            const float mn0 = fmaxf(m0, mx0), mn1 = fmaxf(m1, mx1);
            const float a0 = __expf(m0 - mn0), a1 = __expf(m1 - mn1);
            float rs0 = 0.f, rs1 = 0.f;
            #pragma unroll
            for (int nn = 0; nn < 8; nn++) {
                float p0 = __expf(s[nn][0] - mn0);
                float p1 = __expf(s[nn][1] - mn0);
                float p2 = __expf(s[nn][2] - mn1);
                float p3 = __expf(s[nn][3] - mn1);
                s[nn][0] = p0; s[nn][1] = p1; s[nn][2] = p2; s[nn][3] = p3;
                rs0 += p0 + p1; rs1 += p2 + p3;
            }
            rs0 += __shfl_xor_sync(0xFFFFFFFFu, rs0, 1);
            rs0 += __shfl_xor_sync(0xFFFFFFFFu, rs0, 2);
            rs1 += __shfl_xor_sync(0xFFFFFFFFu, rs1, 1);
            rs1 += __shfl_xor_sync(0xFFFFFFFFu, rs1, 2);

            m0 = mn0; m1 = mn1;
            l0 = l0 * a0 + rs0;
            l1 = l1 * a1 + rs1;

            #pragma unroll
            for (int n = 0; n < 16; n++) {
                O[n][0] *= a0; O[n][1] *= a0;
                O[n][2] *= a1; O[n][3] *= a1;
            }

            // ---- P -> per-warp smem (bf16, A-layout) ----
            __nv_bfloat16* Pw = Ps + w * 16 * FVP;
            #pragma unroll
            for (int nn = 0; nn < 8; nn++) {
                *(unsigned*)&Pw[ lg      * FVP + nn*8 + lt*2] = bf2pack(s[nn][0], s[nn][1]);
                *(unsigned*)&Pw[(lg + 8) * FVP + nn*8 + lt*2] = bf2pack(s[nn][2], s[nn][3]);
            }
            __syncwarp();

            // ---- O += P @ V ----
            #pragma unroll
            for (int kk = 0; kk < 64; kk += 16) {
                unsigned af[4];
                af[0] = *(const unsigned*)&Pw[ lg      * FVP + kk + lt*2    ];
                af[1] = *(const unsigned*)&Pw[(lg + 8) * FVP + kk + lt*2    ];
                af[2] = *(const unsigned*)&Pw[ lg      * FVP + kk + lt*2 + 8];
                af[3] = *(const unsigned*)&Pw[(lg + 8) * FVP + kk + lt*2 + 8];
                #pragma unroll
                for (int n = 0; n < 16; n++) {
                    unsigned bf2r[2];
                    bf2r[0] = *(const unsigned*)&Vst[(n*8 + lg) * FVP + kk + lt*2    ];
                    bf2r[1] = *(const unsigned*)&Vst[(n*8 + lg) * FVP + kk + lt*2 + 8];
                    mma16(O[n], af, bf2r);
                }
            }
        }
    }

    // ---- write ctx (normalized, bf16 for O-proj) ----
    const float inv0 = 1.f / l0, inv1 = 1.f / l1;
    __nv_bfloat16* Cg = ctx + ((size_t)(b * LL + qr0)) * HE + h * EE;
    #pragma unroll
    for (int n = 0; n < 16; n++) {
        const int c = n * 8 + lt * 2;
        *(unsigned*)(Cg + (size_t)lg       * HE + c) = bf2pack(O[n][0]*inv0, O[n][1]*inv0);
        *(unsigned*)(Cg + (size_t)(lg + 8) * HE + c) = bf2pack(O[n][2]*inv1, O[n][3]*inv1);
    }
}

// ============================================================
// Epilogue: out = LayerNorm(x + gelu_erf(ypre)) * gamma + beta
// ============================================================
__global__ __launch_bounds__(256)
void epilogue_ln(const float* __restrict__ x, const float* __restrict__ ypre,
                 const float* __restrict__ gamma, const float* __restrict__ beta,
                 float* __restrict__ out)
{
    const int row = blockIdx.x;
    const int tid = threadIdx.x;
    const float* xr = x    + (size_t)row*DD;
    const float* yr = ypre + (size_t)row*DD;
    float* outr     = out  + (size_t)row*DD;

    float vals[8];
    float s = 0.f, s2 = 0.f;
    #pragma unroll
    for (int k = 0; k < 8; ++k) {
        const int c = tid + k*256;
        const float v = yr[c];
        const float g = 0.5f*v*(1.f + erff(v*0.70710678118654752f));
        const float r = xr[c] + g;
        vals[k] = r;
        s += r; s2 += r*r;
    }

    __shared__ float red[2][8];
    #pragma unroll
    for (int off = 16; off > 0; off >>= 1) {
        s  += __shfl_down_sync(0xFFFFFFFFu, s,  off);
        s2 += __shfl_down_sync(0xFFFFFFFFu, s2, off);
    }
    if ((tid & 31) == 0) { red[0][tid>>5] = s; red[1][tid>>5] = s2; }
    __syncthreads();
    float ts = 0.f, ts2 = 0.f;
    #pragma unroll
    for (int w = 0; w < 8; w++) { ts += red[0][w]; ts2 += red[1][w]; }

    const float mean = ts * (1.f/2048.f);
    const float var  = ts2 * (1.f/2048.f) - mean*mean;
    const float inv  = rsqrtf(var + 1e-5f);

    #pragma unroll
    for (int k = 0; k < 8; ++k) {
        const int c = tid + k*256;
        outr[c] = (vals[k] - mean)*inv*gamma[c] + beta[c];
    }
}

// ============================================================
// Launch
// ============================================================
extern "C" void kernel_launch(void* const* d_in, const int* in_sizes, int n_in,
                              void* d_out, int out_size)
{
    const float* x     = (const float*)d_in[0];
    const float* Wq    = (const float*)d_in[1];
    const float* bq    = (const float*)d_in[2];
    const float* Wk    = (const float*)d_in[3];
    const float* bk    = (const float*)d_in[4];
    const float* Wv    = (const float*)d_in[5];
    const float* bv    = (const float*)d_in[6];
    const float* Wo    = (const float*)d_in[7];
    const float* bo    = (const float*)d_in[8];
    const float* gamma = (const float*)d_in[9];
    const float* beta  = (const float*)d_in[10];
    float* out = (float*)d_out;

    __nv_bfloat16 *xb, *Wqt, *Wkvt, *Wot, *Qb, *KVb, *CTXb;
    float *bkv, *Y;
    cudaGetSymbolAddress((void**)&xb,   g_xb);
    cudaGetSymbolAddress((void**)&Wqt,  g_Wqt);
    cudaGetSymbolAddress((void**)&Wkvt, g_Wkvt);
    cudaGetSymbolAddress((void**)&Wot,  g_Wot);
    cudaGetSymbolAddress((void**)&bkv,  g_bkv);
    cudaGetSymbolAddress((void**)&Qb,   g_Qb);
    cudaGetSymbolAddress((void**)&KVb,  g_KVb);
    cudaGetSymbolAddress((void**)&CTXb, g_CTXb);
    cudaGetSymbolAddress((void**)&Y,    g_Y);

    const dim3 blk(256);

    // ---- operand conversion (one-shot per launch) ----
    f32_to_bf16_k<<<(ML*DD/4 + 255)/256, blk>>>((const float4*)x, (uint2*)xb, ML*DD/4);
    transpose_bf16_k<<<dim3(HE/32,  DD/32), blk>>>(Wq, Wqt, DD, HE);
    transpose_bf16_k<<<dim3(KVE/32, DD/32), blk>>>(Wk, Wkvt,            DD, KVE);
    transpose_bf16_k<<<dim3(KVE/32, DD/32), blk>>>(Wv, Wkvt + (size_t)KVE*DD, DD, KVE);
    transpose_bf16_k<<<dim3(DD/32,  HE/32), blk>>>(Wo, Wot, HE, DD);
    concat_bias_k<<<4, 256>>>(bk, bv, bkv);

    // ---- projections (bf16 tensor-core) ----
    gemm_bf16<true><<<dim3(HE/128,  ML/128), blk>>>(xb, Wqt,  bq,  Qb,  ML, HE,  DD, HE);
    gemm_bf16<true><<<dim3(KVN/128, ML/128), blk>>>(xb, Wkvt, bkv, KVb, ML, KVN, DD, KVN);

    // ---- causal GQA flash attention ----
    const size_t fl_smem = (size_t)FL_SMEM_HALVES * sizeof(__nv_bfloat16);
    cudaFuncSetAttribute(flash_bf16, cudaFuncAttributeMaxDynamicSharedMemorySize,
                         (int)fl_smem);
    flash_bf16<<<dim3(LL/128, BB*HH), blk, fl_smem>>>(Qb, KVb, CTXb);

    // ---- output projection (fp32 out) ----
    gemm_bf16<false><<<dim3(DD/128, ML/128), blk>>>(CTXb, Wot, bo, Y, ML, DD, HE, DD);

    // ---- GELU + residual + LayerNorm ----
    epilogue_ln<<<ML, 256>>>(x, Y, gamma, beta, out);
}

// round 9
// speedup vs baseline: 7.1332x; 1.1538x over previous
#include <cuda_runtime.h>
#include <cuda_bf16.h>
#include <math.h>
#include <stdint.h>

// Problem constants
#define BB   2
#define LL   2048
#define DD   2048
#define HH   16
#define KVH  4
#define EE   128
#define ML   (BB*LL)        // 4096 rows total
#define HE   (HH*EE)        // 2048
#define KVE  (KVH*EE)       // 512
#define QKVN 3072           // fused Q|K|V projection width

// -------- scratch (device globals; no allocation allowed) --------
__device__ __nv_bfloat16 g_xb[ML*DD];         // x in bf16
__device__ __nv_bfloat16 g_Wqkvt[QKVN*DD];    // [Wq|Wk|Wv]^T [N=3072][K=2048] bf16
__device__ __nv_bfloat16 g_Wot[DD*HE];        // Wo^T [N=2048][K=2048] bf16
__device__ float         g_bqkv[QKVN];        // bq|bk|bv
__device__ __nv_bfloat16 g_QKV[ML*QKVN];      // fused QKV output, row stride 3072
__device__ __nv_bfloat16 g_CTXb[ML*HE];       // attention output bf16
__device__ float         g_Y[ML*DD];          // pre-GELU O-proj output fp32

// ---------------- helpers ----------------
__device__ __forceinline__ void mma16(float* d, const unsigned* a, const unsigned* b) {
    asm volatile(
        "mma.sync.aligned.m16n8k16.row.col.f32.bf16.bf16.f32 "
        "{%0,%1,%2,%3}, {%4,%5,%6,%7}, {%8,%9}, {%0,%1,%2,%3};\n"
        : "+f"(d[0]), "+f"(d[1]), "+f"(d[2]), "+f"(d[3])
        : "r"(a[0]), "r"(a[1]), "r"(a[2]), "r"(a[3]),
          "r"(b[0]), "r"(b[1]));
}

__device__ __forceinline__ void ldsm4(unsigned* r, unsigned addr) {
    asm volatile("ldmatrix.sync.aligned.m8n8.x4.shared.b16 {%0,%1,%2,%3}, [%4];"
                 : "=r"(r[0]), "=r"(r[1]), "=r"(r[2]), "=r"(r[3]) : "r"(addr));
}

__device__ __forceinline__ void ldsm4t(unsigned* r, unsigned addr) {
    asm volatile("ldmatrix.sync.aligned.m8n8.x4.trans.shared.b16 {%0,%1,%2,%3}, [%4];"
                 : "=r"(r[0]), "=r"(r[1]), "=r"(r[2]), "=r"(r[3]) : "r"(addr));
}

__device__ __forceinline__ void cp16(unsigned smem_dst, const void* gmem_src) {
    asm volatile("cp.async.cg.shared.global [%0], [%1], 16;\n" :: "r"(smem_dst), "l"(gmem_src));
}

__device__ __forceinline__ unsigned bf2pack(float x, float y) {
    __nv_bfloat162 v = __float22bfloat162_rn(make_float2(x, y));
    return *(unsigned*)&v;
}

__device__ __forceinline__ unsigned smem_u32(const void* p) {
    unsigned a;
    asm("{ .reg .u64 t; cvta.to.shared.u64 t, %1; cvt.u32.u64 %0, t; }" : "=r"(a) : "l"(p));
    return a;
}

// ============================================================
// prep kernels
// ============================================================
__global__ __launch_bounds__(256)
void f32_to_bf16_k(const float4* __restrict__ in, uint2* __restrict__ out, int n4)
{
    int i = blockIdx.x * 256 + threadIdx.x;
    if (i < n4) {
        float4 v = in[i];
        uint2 o;
        o.x = bf2pack(v.x, v.y);
        o.y = bf2pack(v.z, v.w);
        out[i] = o;
    }
}

// W[Kd][Nd] fp32 -> Wt[Nd][Kd] bf16 (tiled transpose)
__global__ __launch_bounds__(256)
void transpose_bf16_k(const float* __restrict__ W, __nv_bfloat16* __restrict__ Wt,
                      int Kd, int Nd)
{
    __shared__ float t[32][33];
    const int n0 = blockIdx.x * 32, k0 = blockIdx.y * 32;
    const int tx = threadIdx.x & 31, ty = threadIdx.x >> 5;
    #pragma unroll
    for (int i = 0; i < 4; i++)
        t[ty + 8*i][tx] = W[(size_t)(k0 + ty + 8*i) * Nd + n0 + tx];
    __syncthreads();
    #pragma unroll
    for (int i = 0; i < 4; i++)
        Wt[(size_t)(n0 + ty + 8*i) * Kd + k0 + tx] = __float2bfloat16(t[tx][ty + 8*i]);
}

__global__ void concat_bias_k(const float* __restrict__ bq, const float* __restrict__ bk,
                              const float* __restrict__ bv, float* __restrict__ bqkv)
{
    int i = blockIdx.x * 256 + threadIdx.x;
    if (i < 2048)        bqkv[i] = bq[i];
    else if (i < 2560)   bqkv[i] = bk[i - 2048];
    else if (i < 3072)   bqkv[i] = bv[i - 2560];
}

// ============================================================
// bf16 tensor-core GEMM (mma.sync + ldmatrix):
// C[M,N] = A[M,K] @ W[K,N] + bias[N];  Bt = W^T [N][K] bf16.
// 128x128 tile, BK=32, cp.async double buffer, 8 warps (64x32 warp tile).
// ============================================================
#define GBK 32

template<bool OUT_BF16>
__global__ __launch_bounds__(256)
void gemm_bf16(const __nv_bfloat16* __restrict__ A, const __nv_bfloat16* __restrict__ Bt,
               const float* __restrict__ bias, void* __restrict__ Cout,
               int M, int N, int K, int ldc)
{
    __shared__ __nv_bfloat16 As[2][128][40];   // [m][k], pad 40 (80B rows, LDSM-safe)
    __shared__ __nv_bfloat16 Bs[2][128][40];   // [n][k]

    const int tid  = threadIdx.x;
    const int w    = tid >> 5, lane = tid & 31;
    const int lt   = lane & 3;
    const int l7   = lane & 7, g = lane >> 3;
    const int wm   = w & 1, wn = w >> 1;        // 2x4 warp grid
    const int bx   = blockIdx.x, by = blockIdx.y;

    const unsigned AsU = smem_u32(&As[0][0][0]);
    const unsigned BsU = smem_u32(&Bs[0][0][0]);
    const unsigned bufB = 128 * 40 * 2;        // bytes per buffer

    const __nv_bfloat16* Ag = A  + (size_t)(by * 128) * K;
    const __nv_bfloat16* Bg = Bt + (size_t)(bx * 128) * K;

    float acc[4][4][4];
    #pragma unroll
    for (int mt = 0; mt < 4; mt++)
        #pragma unroll
        for (int nt = 0; nt < 4; nt++)
            #pragma unroll
            for (int f = 0; f < 4; f++) acc[mt][nt][f] = 0.f;

    auto issue = [&](int buf, int k0) {
        #pragma unroll
        for (int i = 0; i < 2; i++) {          // A tile 128x32: 512 16B chunks
            int q = tid + i * 256;
            int r = q >> 2, c8 = (q & 3) * 8;
            cp16(AsU + buf*bufB + (r*40 + c8)*2, Ag + (size_t)r * K + k0 + c8);
        }
        #pragma unroll
        for (int i = 0; i < 2; i++) {          // B tile 128x32
            int q = tid + i * 256;
            int r = q >> 2, c8 = (q & 3) * 8;
            cp16(BsU + buf*bufB + (r*40 + c8)*2, Bg + (size_t)r * K + k0 + c8);
        }
        asm volatile("cp.async.commit_group;\n");
    };

    issue(0, 0);
    const int KT = K / GBK;

    for (int kt = 0; kt < KT; ++kt) {
        asm volatile("cp.async.wait_group 0;\n");
        __syncthreads();
        if (kt + 1 < KT) issue((kt + 1) & 1, (kt + 1) * GBK);
        const int buf = kt & 1;
        const unsigned aBase = AsU + buf*bufB;
        const unsigned bBase = BsU + buf*bufB;

        #pragma unroll
        for (int k8 = 0; k8 < GBK; k8 += 16) {
            // A fragments: 4 m-tiles via ldmatrix.x4
            unsigned af[4][4];
            #pragma unroll
            for (int mt = 0; mt < 4; mt++) {
                int row = wm*64 + mt*16 + (g & 1)*8 + l7;
                int col = k8 + (g >> 1)*8;
                ldsm4(af[mt], aBase + (row*40 + col)*2);
            }
            // B fragments: 4 n-tiles via 2x ldmatrix.x4
            unsigned bf[4][2];
            #pragma unroll
            for (int np = 0; np < 2; np++) {
                int row = wn*32 + np*16 + (g >> 1)*8 + l7;
                int col = k8 + (g & 1)*8;
                unsigned r[4];
                ldsm4(r, bBase + (row*40 + col)*2);
                bf[2*np][0] = r[0]; bf[2*np][1] = r[1];
                bf[2*np+1][0] = r[2]; bf[2*np+1][1] = r[3];
            }
            #pragma unroll
            for (int mt = 0; mt < 4; mt++)
                #pragma unroll
                for (int nt = 0; nt < 4; nt++)
                    mma16(acc[mt][nt], af[mt], bf[nt]);
        }
    }

    const int lg = lane >> 2;
    #pragma unroll
    for (int mt = 0; mt < 4; mt++) {
        const int r0 = by * 128 + wm * 64 + mt * 16 + lg;
        #pragma unroll
        for (int nt = 0; nt < 4; nt++) {
            const int c = bx * 128 + wn * 32 + nt * 8 + lt * 2;
            const float b0 = bias[c], b1 = bias[c + 1];
            if (OUT_BF16) {
                __nv_bfloat16* Cb = (__nv_bfloat16*)Cout;
                *(unsigned*)(Cb + (size_t)r0       * ldc + c) =
                    bf2pack(acc[mt][nt][0] + b0, acc[mt][nt][1] + b1);
                *(unsigned*)(Cb + (size_t)(r0 + 8) * ldc + c) =
                    bf2pack(acc[mt][nt][2] + b0, acc[mt][nt][3] + b1);
            } else {
                float* Cf = (float*)Cout;
                float2 o0, o1;
                o0.x = acc[mt][nt][0] + b0;  o0.y = acc[mt][nt][1] + b1;
                o1.x = acc[mt][nt][2] + b0;  o1.y = acc[mt][nt][3] + b1;
                *(float2*)(Cf + (size_t)r0       * ldc + c) = o0;
                *(float2*)(Cf + (size_t)(r0 + 8) * ldc + c) = o1;
            }
        }
    }
}

// ============================================================
// Flash attention (causal, GQA), bf16 mma.sync + ldmatrix.
// Q fragments register-resident; V via ldmatrix.trans (no transpose pass);
// P converted C-frag -> A-frag in registers; K/V cp.async double-buffered.
// Block: 128 q-rows, 8 warps x 16 rows, Bc=64, E=128.
// ============================================================
#define FQP 136   // row pad in halves (272B, LDSM conflict-free)
// halves: Qs 128*136 + (K0,K1,V0,V1) 4*64*136
#define FL_SMEM_BYTES ((128*FQP + 4*64*FQP) * 2)

__global__ __launch_bounds__(256)
void flash_bf16(const __nv_bfloat16* __restrict__ QKV, __nv_bfloat16* __restrict__ ctx)
{
    extern __shared__ __nv_bfloat16 sm[];
    const unsigned QsU = smem_u32(sm);
    const unsigned tileB = 64 * FQP * 2;       // bytes per K/V tile
    const unsigned KsU = QsU + 128 * FQP * 2;  // K buffers at +0, +tileB
    const unsigned VsU = KsU + 2 * tileB;      // V buffers

    const int tid  = threadIdx.x;
    const int w    = tid >> 5, lane = tid & 31;
    const int lg   = lane >> 2, lt = lane & 3;
    const int l7   = lane & 7, g = lane >> 3;
    const int h2   = w >> 2, wq = w & 3;
    const int bh   = blockIdx.y;
    const int b    = bh / HH, h = bh % HH, kvh = h % KVH;
    const int qb   = blockIdx.x * 128;
    const int qrl  = h2 * 64 + wq * 16;        // warp local q-row base
    const int qr0  = qb + qrl;
    const float scale = 0.08838834764831845f;  // 1/sqrt(128)

    const __nv_bfloat16* Kg0 = QKV + (size_t)(b * LL) * QKVN + 2048 + kvh * EE;

    auto issue = [&](int buf, int kb) {
        const __nv_bfloat16* Kg = Kg0 + (size_t)kb * QKVN;
        const __nv_bfloat16* Vg = Kg + KVE;
        #pragma unroll
        for (int i = 0; i < 4; i++) {          // 64 rows x 8 chunks each of K and V
            int q = tid + i * 256;
            int r = q >> 4, c8 = (q & 15) * 8;
            cp16(KsU + buf*tileB + (r*FQP + c8)*2, Kg + (size_t)r * QKVN + c8);
            cp16(VsU + buf*tileB + (r*FQP + c8)*2, Vg + (size_t)r * QKVN + c8);
        }
        asm volatile("cp.async.commit_group;\n");
    };

    // kick off tile 0 loads, then stage Q
    issue(0, 0);
    {
        const __nv_bfloat16* Qg = QKV + ((size_t)(b * LL + qb)) * QKVN + h * EE;
        #pragma unroll
        for (int i = 0; i < 8; i++) {
            int q = tid + i * 256;
            int r = q >> 4, c8 = (q & 15) * 8;
            *(uint4*)(sm + r * FQP + c8) = *(const uint4*)(Qg + (size_t)r * QKVN + c8);
        }
    }
    __syncthreads();

    // Q fragments -> registers (reused across all k-tiles)
    unsigned qf[8][4];
    #pragma unroll
    for (int e8 = 0; e8 < 8; e8++) {
        int row = qrl + (g & 1)*8 + l7;
        int col = e8*16 + (g >> 1)*8;
        ldsm4(qf[e8], QsU + (row*FQP + col)*2);
    }

    float O[16][4];
    #pragma unroll
    for (int n = 0; n < 16; n++)
        #pragma unroll
        for (int f = 0; f < 4; f++) O[n][f] = 0.f;
    float m0 = -INFINITY, m1 = -INFINITY, l0 = 0.f, l1 = 0.f;

    const int ntiles = (qb >> 6) + 2;
    for (int t = 0; t < ntiles; ++t) {
        const int kb = t * 64;
        asm volatile("cp.async.wait_group 0;\n");
        __syncthreads();
        if (t + 1 < ntiles) issue((t + 1) & 1, kb + 64);
        const int buf = t & 1;
        const unsigned kBase = KsU + buf*tileB;
        const unsigned vBase = VsU + buf*tileB;

        if (kb <= qr0 + 15) {
            // ---- S = Q @ K^T (16x64 per warp) ----
            float s[8][4];
            #pragma unroll
            for (int nn = 0; nn < 8; nn++)
                #pragma unroll
                for (int f = 0; f < 4; f++) s[nn][f] = 0.f;

            #pragma unroll
            for (int e8 = 0; e8 < 8; e8++) {
                #pragma unroll
                for (int np = 0; np < 4; np++) {
                    int row = np*16 + (g >> 1)*8 + l7;
                    int col = e8*16 + (g & 1)*8;
                    unsigned r[4];
                    ldsm4(r, kBase + (row*FQP + col)*2);
                    mma16(s[2*np],     qf[e8], r);
                    mma16(s[2*np + 1], qf[e8], r + 2);
                }
            }
            #pragma unroll
            for (int nn = 0; nn < 8; nn++)
                #pragma unroll
                for (int f = 0; f < 4; f++) s[nn][f] *= scale;

            // ---- causal mask (diagonal tile only) ----
            if (kb + 63 > qr0) {
                const int r0g = qr0 + lg, r1g = qr0 + lg + 8;
                #pragma unroll
                for (int nn = 0; nn < 8; nn++) {
                    const int c0 = kb + nn * 8 + lt * 2;
                    if (c0     > r0g) s[nn][0] = -1e30f;
                    if (c0 + 1 > r0g) s[nn][1] = -1e30f;
                    if (c0     > r1g) s[nn][2] = -1e30f;
                    if (c0 + 1 > r1g) s[nn][3] = -1e30f;
                }
            }

            // ---- online softmax (rows lg, lg+8) ----
            float mx0 = -1e30f, mx1 = -1e30f;
            #pragma unroll
            for (int nn = 0; nn < 8; nn++) {
                mx0 = fmaxf(mx0, fmaxf(s[nn][0], s[nn][1]));
                mx1 = fmaxf(mx1, fmaxf(s[nn][2], s[nn][3]));
            }
            mx0 = fmaxf(mx0, __shfl_xor_sync(0xFFFFFFFFu, mx0, 1));
            mx0 = fmaxf(mx0, __shfl_xor_sync(0xFFFFFFFFu, mx0, 2));
            mx1 = fmaxf(mx1, __shfl_xor_sync(0xFFFFFFFFu, mx1, 1));
            mx1 = fmaxf(mx1, __shfl_xor_sync(0xFFFFFFFFu, mx1, 2));

            const float mn0 = fmaxf(m0, mx0), mn1 = fmaxf(m1, mx1);
            const float a0 = __expf(m0 - mn0), a1 = __expf(m1 - mn1);
            float rs0 = 0.f, rs1 = 0.f;
            #pragma unroll
            for (int nn = 0; nn < 8; nn++) {
                float p0 = __expf(s[nn][0] - mn0);
                float p1 = __expf(s[nn][1] - mn0);
                float p2 = __expf(s[nn][2] - mn1);
                float p3 = __expf(s[nn][3] - mn1);
                s[nn][0] = p0; s[nn][1] = p1; s[nn][2] = p2; s[nn][3] = p3;
                rs0 += p0 + p1; rs1 += p2 + p3;
            }
            rs0 += __shfl_xor_sync(0xFFFFFFFFu, rs0, 1);
            rs0 += __shfl_xor_sync(0xFFFFFFFFu, rs0, 2);
            rs1 += __shfl_xor_sync(0xFFFFFFFFu, rs1, 1);
            rs1 += __shfl_xor_sync(0xFFFFFFFFu, rs1, 2);

            m0 = mn0; m1 = mn1;
            l0 = l0 * a0 + rs0;
            l1 = l1 * a1 + rs1;

            #pragma unroll
            for (int n = 0; n < 16; n++) {
                O[n][0] *= a0; O[n][1] *= a0;
                O[n][2] *= a1; O[n][3] *= a1;
            }

            // ---- O += P @ V : P converted C-frag -> A-frag in registers ----
            #pragma unroll
            for (int kk = 0; kk < 4; kk++) {
                unsigned pa[4];
                pa[0] = bf2pack(s[2*kk][0],     s[2*kk][1]);
                pa[1] = bf2pack(s[2*kk][2],     s[2*kk][3]);
                pa[2] = bf2pack(s[2*kk + 1][0], s[2*kk + 1][1]);
                pa[3] = bf2pack(s[2*kk + 1][2], s[2*kk + 1][3]);
                #pragma unroll
                for (int ne = 0; ne < 8; ne++) {
                    int row = kk*16 + (g & 1)*8 + l7;
                    int col = ne*16 + (g >> 1)*8;
                    unsigned r[4];
                    ldsm4t(r, vBase + (row*FQP + col)*2);
                    mma16(O[2*ne],     pa, r);
                    mma16(O[2*ne + 1], pa, r + 2);
                }
            }
        }
    }

    // ---- write ctx (normalized, bf16) ----
    const float inv0 = 1.f / l0, inv1 = 1.f / l1;
    __nv_bfloat16* Cg = ctx + ((size_t)(b * LL + qr0)) * HE + h * EE;
    #pragma unroll
    for (int n = 0; n < 16; n++) {
        const int c = n * 8 + lt * 2;
        *(unsigned*)(Cg + (size_t)lg       * HE + c) = bf2pack(O[n][0]*inv0, O[n][1]*inv0);
        *(unsigned*)(Cg + (size_t)(lg + 8) * HE + c) = bf2pack(O[n][2]*inv1, O[n][3]*inv1);
    }
}

// ============================================================
// Epilogue: out = LayerNorm(x + gelu_erf(ypre)) * gamma + beta
// ============================================================
__global__ __launch_bounds__(256)
void epilogue_ln(const float* __restrict__ x, const float* __restrict__ ypre,
                 const float* __restrict__ gamma, const float* __restrict__ beta,
                 float* __restrict__ out)
{
    const int row = blockIdx.x;
    const int tid = threadIdx.x;
    const float* xr = x    + (size_t)row*DD;
    const float* yr = ypre + (size_t)row*DD;
    float* outr     = out  + (size_t)row*DD;

    float vals[8];
    float s = 0.f, s2 = 0.f;
    #pragma unroll
    for (int k = 0; k < 8; ++k) {
        const int c = tid + k*256;
        const float v = yr[c];
        const float gl = 0.5f*v*(1.f + erff(v*0.70710678118654752f));
        const float r = xr[c] + gl;
        vals[k] = r;
        s += r; s2 += r*r;
    }

    __shared__ float red[2][8];
    #pragma unroll
    for (int off = 16; off > 0; off >>= 1) {
        s  += __shfl_down_sync(0xFFFFFFFFu, s,  off);
        s2 += __shfl_down_sync(0xFFFFFFFFu, s2, off);
    }
    if ((tid & 31) == 0) { red[0][tid>>5] = s; red[1][tid>>5] = s2; }
    __syncthreads();
    float ts = 0.f, ts2 = 0.f;
    #pragma unroll
    for (int w = 0; w < 8; w++) { ts += red[0][w]; ts2 += red[1][w]; }

    const float mean = ts * (1.f/2048.f);
    const float var  = ts2 * (1.f/2048.f) - mean*mean;
    const float inv  = rsqrtf(var + 1e-5f);

    #pragma unroll
    for (int k = 0; k < 8; ++k) {
        const int c = tid + k*256;
        outr[c] = (vals[k] - mean)*inv*gamma[c] + beta[c];
    }
}

// ============================================================
// Launch
// ============================================================
extern "C" void kernel_launch(void* const* d_in, const int* in_sizes, int n_in,
                              void* d_out, int out_size)
{
    const float* x     = (const float*)d_in[0];
    const float* Wq    = (const float*)d_in[1];
    const float* bq    = (const float*)d_in[2];
    const float* Wk    = (const float*)d_in[3];
    const float* bk    = (const float*)d_in[4];
    const float* Wv    = (const float*)d_in[5];
    const float* bv    = (const float*)d_in[6];
    const float* Wo    = (const float*)d_in[7];
    const float* bo    = (const float*)d_in[8];
    const float* gamma = (const float*)d_in[9];
    const float* beta  = (const float*)d_in[10];
    float* out = (float*)d_out;

    __nv_bfloat16 *xb, *Wqkvt, *Wot, *QKV, *CTXb;
    float *bqkv, *Y;
    cudaGetSymbolAddress((void**)&xb,    g_xb);
    cudaGetSymbolAddress((void**)&Wqkvt, g_Wqkvt);
    cudaGetSymbolAddress((void**)&Wot,   g_Wot);
    cudaGetSymbolAddress((void**)&bqkv,  g_bqkv);
    cudaGetSymbolAddress((void**)&QKV,   g_QKV);
    cudaGetSymbolAddress((void**)&CTXb,  g_CTXb);
    cudaGetSymbolAddress((void**)&Y,     g_Y);

    const dim3 blk(256);

    // ---- operand prep ----
    f32_to_bf16_k<<<(ML*DD/4 + 255)/256, blk>>>((const float4*)x, (uint2*)xb, ML*DD/4);
    transpose_bf16_k<<<dim3(HE/32,  DD/32), blk>>>(Wq, Wqkvt,                   DD, HE);
    transpose_bf16_k<<<dim3(KVE/32, DD/32), blk>>>(Wk, Wqkvt + (size_t)2048*DD, DD, KVE);
    transpose_bf16_k<<<dim3(KVE/32, DD/32), blk>>>(Wv, Wqkvt + (size_t)2560*DD, DD, KVE);
    transpose_bf16_k<<<dim3(DD/32,  HE/32), blk>>>(Wo, Wot, HE, DD);
    concat_bias_k<<<12, 256>>>(bq, bk, bv, bqkv);

    // ---- fused QKV projection ----
    gemm_bf16<true><<<dim3(QKVN/128, ML/128), blk>>>(xb, Wqkvt, bqkv, QKV, ML, QKVN, DD, QKVN);

    // ---- causal GQA flash attention ----
    cudaFuncSetAttribute(flash_bf16, cudaFuncAttributeMaxDynamicSharedMemorySize, FL_SMEM_BYTES);
    flash_bf16<<<dim3(LL/128, BB*HH), blk, FL_SMEM_BYTES>>>(QKV, CTXb);

    // ---- output projection (fp32 out) ----
    gemm_bf16<false><<<dim3(DD/128, ML/128), blk>>>(CTXb, Wot, bo, Y, ML, DD, HE, DD);

    // ---- GELU + residual + LayerNorm ----
    epilogue_ln<<<ML, 256>>>(x, Y, gamma, beta, out);
}

// round 10
// speedup vs baseline: 8.0964x; 1.1350x over previous
#include <cuda_runtime.h>
#include <cuda_bf16.h>
#include <math.h>
#include <stdint.h>

// Problem constants
#define BB   2
#define LL   2048
#define DD   2048
#define HH   16
#define KVH  4
#define EE   128
#define ML   (BB*LL)        // 4096 rows total
#define HE   (HH*EE)        // 2048
#define KVE  (KVH*EE)       // 512
#define QKVN 3072           // fused Q|K|V projection width

// -------- scratch (device globals; no allocation allowed) --------
__device__ __nv_bfloat16 g_xb[ML*DD];         // x in bf16
__device__ __nv_bfloat16 g_Wqkvt[QKVN*DD];    // [Wq|Wk|Wv]^T [N=3072][K=2048] bf16
__device__ __nv_bfloat16 g_Wot[DD*HE];        // Wo^T [N=2048][K=2048] bf16
__device__ float         g_bqkv[QKVN];        // bq|bk|bv
__device__ __nv_bfloat16 g_QKV[ML*QKVN];      // fused QKV output, row stride 3072
__device__ __nv_bfloat16 g_CTXb[ML*HE];       // attention output bf16
__device__ float         g_Y[ML*DD];          // pre-GELU O-proj output fp32

// ---------------- helpers ----------------
__device__ __forceinline__ void mma16(float* d, const unsigned* a, const unsigned* b) {
    asm volatile(
        "mma.sync.aligned.m16n8k16.row.col.f32.bf16.bf16.f32 "
        "{%0,%1,%2,%3}, {%4,%5,%6,%7}, {%8,%9}, {%0,%1,%2,%3};\n"
        : "+f"(d[0]), "+f"(d[1]), "+f"(d[2]), "+f"(d[3])
        : "r"(a[0]), "r"(a[1]), "r"(a[2]), "r"(a[3]),
          "r"(b[0]), "r"(b[1]));
}

__device__ __forceinline__ void ldsm4(unsigned* r, unsigned addr) {
    asm volatile("ldmatrix.sync.aligned.m8n8.x4.shared.b16 {%0,%1,%2,%3}, [%4];"
                 : "=r"(r[0]), "=r"(r[1]), "=r"(r[2]), "=r"(r[3]) : "r"(addr));
}

__device__ __forceinline__ void ldsm4t(unsigned* r, unsigned addr) {
    asm volatile("ldmatrix.sync.aligned.m8n8.x4.trans.shared.b16 {%0,%1,%2,%3}, [%4];"
                 : "=r"(r[0]), "=r"(r[1]), "=r"(r[2]), "=r"(r[3]) : "r"(addr));
}

__device__ __forceinline__ void cp16(unsigned smem_dst, const void* gmem_src) {
    asm volatile("cp.async.cg.shared.global [%0], [%1], 16;\n" :: "r"(smem_dst), "l"(gmem_src));
}

__device__ __forceinline__ unsigned bf2pack(float x, float y) {
    __nv_bfloat162 v = __float22bfloat162_rn(make_float2(x, y));
    return *(unsigned*)&v;
}

__device__ __forceinline__ unsigned smem_u32(const void* p) {
    unsigned a;
    asm("{ .reg .u64 t; cvta.to.shared.u64 t, %1; cvt.u32.u64 %0, t; }" : "=r"(a) : "l"(p));
    return a;
}

// ============================================================
// Fused prep kernel: one launch does
//   [0,8192)       x fp32 -> bf16 (float4 granularity)
//   [8192,12288)   Wq transpose  -> Wqkvt[0]
//   [12288,13312)  Wk transpose  -> Wqkvt + 2048*DD
//   [13312,14336)  Wv transpose  -> Wqkvt + 2560*DD
//   [14336,18432)  Wo transpose  -> Wot
//   [18432,18444)  bias concat
// ============================================================
#define PREP_BLOCKS 18444

__device__ __forceinline__ void transp_tile(float (*t)[33],
                                            const float* __restrict__ W,
                                            __nv_bfloat16* __restrict__ Wt,
                                            int Kd, int Nd, int bx, int by, int tid)
{
    const int n0 = bx * 32, k0 = by * 32;
    const int tx = tid & 31, ty = tid >> 5;
    #pragma unroll
    for (int i = 0; i < 4; i++)
        t[ty + 8*i][tx] = W[(size_t)(k0 + ty + 8*i) * Nd + n0 + tx];
    __syncthreads();
    #pragma unroll
    for (int i = 0; i < 4; i++)
        Wt[(size_t)(n0 + ty + 8*i) * Kd + k0 + tx] = __float2bfloat16(t[tx][ty + 8*i]);
}

__global__ __launch_bounds__(256)
void prep_all(const float* __restrict__ x,
              const float* __restrict__ Wq, const float* __restrict__ Wk,
              const float* __restrict__ Wv, const float* __restrict__ Wo,
              const float* __restrict__ bq, const float* __restrict__ bk,
              const float* __restrict__ bv,
              __nv_bfloat16* __restrict__ xb, __nv_bfloat16* __restrict__ Wqkvt,
              __nv_bfloat16* __restrict__ Wot, float* __restrict__ bqkv)
{
    __shared__ float t[32][33];
    const int bid = blockIdx.x;
    const int tid = threadIdx.x;

    if (bid < 8192) {
        // x convert: 2,097,152 float4s
        int i = bid * 256 + tid;
        float4 v = ((const float4*)x)[i];
        uint2 o;
        o.x = bf2pack(v.x, v.y);
        o.y = bf2pack(v.z, v.w);
        ((uint2*)xb)[i] = o;
    } else if (bid < 12288) {
        int tt = bid - 8192;                    // Wq: 64 x 64 tiles
        transp_tile(t, Wq, Wqkvt, DD, HE, tt & 63, tt >> 6, tid);
    } else if (bid < 13312) {
        int tt = bid - 12288;                   // Wk: 16 x 64 tiles
        transp_tile(t, Wk, Wqkvt + (size_t)2048*DD, DD, KVE, tt & 15, tt >> 4, tid);
    } else if (bid < 14336) {
        int tt = bid - 13312;                   // Wv: 16 x 64 tiles
        transp_tile(t, Wv, Wqkvt + (size_t)2560*DD, DD, KVE, tt & 15, tt >> 4, tid);
    } else if (bid < 18432) {
        int tt = bid - 14336;                   // Wo: 64 x 64 tiles
        transp_tile(t, Wo, Wot, HE, DD, tt & 63, tt >> 6, tid);
    } else {
        int i = (bid - 18432) * 256 + tid;      // bias concat
        if (i < 2048)        bqkv[i] = bq[i];
        else if (i < 2560)   bqkv[i] = bk[i - 2048];
        else if (i < 3072)   bqkv[i] = bv[i - 2560];
    }
}

// ============================================================
// bf16 tensor-core GEMM (mma.sync + ldmatrix):
// C[M,N] = A[M,K] @ W[K,N] + bias[N];  Bt = W^T [N][K] bf16.
// 128x128 tile, BK=64, cp.async double buffer (dynamic smem),
// 8 warps (64x32 warp tile).
// ============================================================
#define GBK  64
#define GPAD 72
#define GTILE_B (128*GPAD*2)          // 18432 bytes per matrix tile
#define GEMM_SMEM (4*GTILE_B)         // A0,A1,B0,B1

template<bool OUT_BF16>
__global__ __launch_bounds__(256)
void gemm_bf16(const __nv_bfloat16* __restrict__ A, const __nv_bfloat16* __restrict__ Bt,
               const float* __restrict__ bias, void* __restrict__ Cout,
               int M, int N, int K, int ldc)
{
    extern __shared__ __nv_bfloat16 gsm[];
    const unsigned AsU = smem_u32(gsm);
    const unsigned BsU = AsU + 2 * GTILE_B;

    const int tid  = threadIdx.x;
    const int w    = tid >> 5, lane = tid & 31;
    const int lt   = lane & 3;
    const int l7   = lane & 7, g = lane >> 3;
    const int wm   = w & 1, wn = w >> 1;        // 2x4 warp grid
    const int bx   = blockIdx.x, by = blockIdx.y;

    const __nv_bfloat16* Ag = A  + (size_t)(by * 128) * K;
    const __nv_bfloat16* Bg = Bt + (size_t)(bx * 128) * K;

    float acc[4][4][4];
    #pragma unroll
    for (int mt = 0; mt < 4; mt++)
        #pragma unroll
        for (int nt = 0; nt < 4; nt++)
            #pragma unroll
            for (int f = 0; f < 4; f++) acc[mt][nt][f] = 0.f;

    auto issue = [&](int buf, int k0) {
        #pragma unroll
        for (int i = 0; i < 4; i++) {          // A tile 128x64: 1024 16B chunks
            int q = tid + i * 256;
            int r = q >> 3, c8 = (q & 7) * 8;
            cp16(AsU + buf*GTILE_B + (r*GPAD + c8)*2, Ag + (size_t)r * K + k0 + c8);
        }
        #pragma unroll
        for (int i = 0; i < 4; i++) {          // B tile 128x64
            int q = tid + i * 256;
            int r = q >> 3, c8 = (q & 7) * 8;
            cp16(BsU + buf*GTILE_B + (r*GPAD + c8)*2, Bg + (size_t)r * K + k0 + c8);
        }
        asm volatile("cp.async.commit_group;\n");
    };

    issue(0, 0);
    const int KT = K / GBK;

    for (int kt = 0; kt < KT; ++kt) {
        asm volatile("cp.async.wait_group 0;\n");
        __syncthreads();
        if (kt + 1 < KT) issue((kt + 1) & 1, (kt + 1) * GBK);
        const int buf = kt & 1;
        const unsigned aBase = AsU + buf*GTILE_B;
        const unsigned bBase = BsU + buf*GTILE_B;

        #pragma unroll
        for (int k8 = 0; k8 < GBK; k8 += 16) {
            unsigned af[4][4];
            #pragma unroll
            for (int mt = 0; mt < 4; mt++) {
                int row = wm*64 + mt*16 + (g & 1)*8 + l7;
                int col = k8 + (g >> 1)*8;
                ldsm4(af[mt], aBase + (row*GPAD + col)*2);
            }
            unsigned bf[4][2];
            #pragma unroll
            for (int np = 0; np < 2; np++) {
                int row = wn*32 + np*16 + (g >> 1)*8 + l7;
                int col = k8 + (g & 1)*8;
                unsigned r[4];
                ldsm4(r, bBase + (row*GPAD + col)*2);
                bf[2*np][0] = r[0]; bf[2*np][1] = r[1];
                bf[2*np+1][0] = r[2]; bf[2*np+1][1] = r[3];
            }
            #pragma unroll
            for (int mt = 0; mt < 4; mt++)
                #pragma unroll
                for (int nt = 0; nt < 4; nt++)
                    mma16(acc[mt][nt], af[mt], bf[nt]);
        }
    }

    const int lg = lane >> 2;
    #pragma unroll
    for (int mt = 0; mt < 4; mt++) {
        const int r0 = by * 128 + wm * 64 + mt * 16 + lg;
        #pragma unroll
        for (int nt = 0; nt < 4; nt++) {
            const int c = bx * 128 + wn * 32 + nt * 8 + lt * 2;
            const float b0 = bias[c], b1 = bias[c + 1];
            if (OUT_BF16) {
                __nv_bfloat16* Cb = (__nv_bfloat16*)Cout;
                *(unsigned*)(Cb + (size_t)r0       * ldc + c) =
                    bf2pack(acc[mt][nt][0] + b0, acc[mt][nt][1] + b1);
                *(unsigned*)(Cb + (size_t)(r0 + 8) * ldc + c) =
                    bf2pack(acc[mt][nt][2] + b0, acc[mt][nt][3] + b1);
            } else {
                float* Cf = (float*)Cout;
                float2 o0, o1;
                o0.x = acc[mt][nt][0] + b0;  o0.y = acc[mt][nt][1] + b1;
                o1.x = acc[mt][nt][2] + b0;  o1.y = acc[mt][nt][3] + b1;
                *(float2*)(Cf + (size_t)r0       * ldc + c) = o0;
                *(float2*)(Cf + (size_t)(r0 + 8) * ldc + c) = o1;
            }
        }
    }
}

// ============================================================
// Flash attention (causal, GQA), bf16 mma.sync + ldmatrix.
// Q fragments register-resident; V via ldmatrix.trans;
// P converted C-frag -> A-frag in registers; K/V cp.async double-buffered.
// Block: 128 q-rows, 8 warps x 16 rows, Bc=64, E=128.
// CTA x-index reversed so longest (most k-tiles) CTAs launch first.
// ============================================================
#define FQP 136   // row pad in halves (272B, LDSM conflict-free)
#define FL_SMEM_BYTES ((128*FQP + 4*64*FQP) * 2)

__global__ __launch_bounds__(256)
void flash_bf16(const __nv_bfloat16* __restrict__ QKV, __nv_bfloat16* __restrict__ ctx)
{
    extern __shared__ __nv_bfloat16 sm[];
    const unsigned QsU = smem_u32(sm);
    const unsigned tileB = 64 * FQP * 2;
    const unsigned KsU = QsU + 128 * FQP * 2;
    const unsigned VsU = KsU + 2 * tileB;

    const int tid  = threadIdx.x;
    const int w    = tid >> 5, lane = tid & 31;
    const int lg   = lane >> 2, lt = lane & 3;
    const int l7   = lane & 7, g = lane >> 3;
    const int h2   = w >> 2, wq = w & 3;
    const int bh   = blockIdx.y;
    const int b    = bh / HH, h = bh % HH, kvh = h % KVH;
    const int bxr  = (int)gridDim.x - 1 - (int)blockIdx.x;   // longest first
    const int qb   = bxr * 128;
    const int qrl  = h2 * 64 + wq * 16;
    const int qr0  = qb + qrl;
    const float scale = 0.08838834764831845f;

    const __nv_bfloat16* Kg0 = QKV + (size_t)(b * LL) * QKVN + 2048 + kvh * EE;

    auto issue = [&](int buf, int kb) {
        const __nv_bfloat16* Kg = Kg0 + (size_t)kb * QKVN;
        const __nv_bfloat16* Vg = Kg + KVE;
        #pragma unroll
        for (int i = 0; i < 4; i++) {
            int q = tid + i * 256;
            int r = q >> 4, c8 = (q & 15) * 8;
            cp16(KsU + buf*tileB + (r*FQP + c8)*2, Kg + (size_t)r * QKVN + c8);
            cp16(VsU + buf*tileB + (r*FQP + c8)*2, Vg + (size_t)r * QKVN + c8);
        }
        asm volatile("cp.async.commit_group;\n");
    };

    issue(0, 0);
    {
        const __nv_bfloat16* Qg = QKV + ((size_t)(b * LL + qb)) * QKVN + h * EE;
        #pragma unroll
        for (int i = 0; i < 8; i++) {
            int q = tid + i * 256;
            int r = q >> 4, c8 = (q & 15) * 8;
            *(uint4*)(sm + r * FQP + c8) = *(const uint4*)(Qg + (size_t)r * QKVN + c8);
        }
    }
    __syncthreads();

    unsigned qf[8][4];
    #pragma unroll
    for (int e8 = 0; e8 < 8; e8++) {
        int row = qrl + (g & 1)*8 + l7;
        int col = e8*16 + (g >> 1)*8;
        ldsm4(qf[e8], QsU + (row*FQP + col)*2);
    }

    float O[16][4];
    #pragma unroll
    for (int n = 0; n < 16; n++)
        #pragma unroll
        for (int f = 0; f < 4; f++) O[n][f] = 0.f;
    float m0 = -INFINITY, m1 = -INFINITY, l0 = 0.f, l1 = 0.f;

    const int ntiles = (qb >> 6) + 2;
    for (int t = 0; t < ntiles; ++t) {
        const int kb = t * 64;
        asm volatile("cp.async.wait_group 0;\n");
        __syncthreads();
        if (t + 1 < ntiles) issue((t + 1) & 1, kb + 64);
        const int buf = t & 1;
        const unsigned kBase = KsU + buf*tileB;
        const unsigned vBase = VsU + buf*tileB;

        if (kb <= qr0 + 15) {
            float s[8][4];
            #pragma unroll
            for (int nn = 0; nn < 8; nn++)
                #pragma unroll
                for (int f = 0; f < 4; f++) s[nn][f] = 0.f;

            #pragma unroll
            for (int e8 = 0; e8 < 8; e8++) {
                #pragma unroll
                for (int np = 0; np < 4; np++) {
                    int row = np*16 + (g >> 1)*8 + l7;
                    int col = e8*16 + (g & 1)*8;
                    unsigned r[4];
                    ldsm4(r, kBase + (row*FQP + col)*2);
                    mma16(s[2*np],     qf[e8], r);
                    mma16(s[2*np + 1], qf[e8], r + 2);
                }
            }
            #pragma unroll
            for (int nn = 0; nn < 8; nn++)
                #pragma unroll
                for (int f = 0; f < 4; f++) s[nn][f] *= scale;

            if (kb + 63 > qr0) {
                const int r0g = qr0 + lg, r1g = qr0 + lg + 8;
                #pragma unroll
                for (int nn = 0; nn < 8; nn++) {
                    const int c0 = kb + nn * 8 + lt * 2;
                    if (c0     > r0g) s[nn][0] = -1e30f;
                    if (c0 + 1 > r0g) s[nn][1] = -1e30f;
                    if (c0     > r1g) s[nn][2] = -1e30f;
                    if (c0 + 1 > r1g) s[nn][3] = -1e30f;
                }
            }

            float mx0 = -1e30f, mx1 = -1e30f;
            #pragma unroll
            for (int nn = 0; nn < 8; nn++) {
                mx0 = fmaxf(mx0, fmaxf(s[nn][0], s[nn][1]));
                mx1 = fmaxf(mx1, fmaxf(s[nn][2], s[nn][3]));
            }
            mx0 = fmaxf(mx0, __shfl_xor_sync(0xFFFFFFFFu, mx0, 1));
            mx0 = fmaxf(mx0, __shfl_xor_sync(0xFFFFFFFFu, mx0, 2));
            mx1 = fmaxf(mx1, __shfl_xor_sync(0xFFFFFFFFu, mx1, 1));
            mx1 = fmaxf(mx1, __shfl_xor_sync(0xFFFFFFFFu, mx1, 2));

            const float mn0 = fmaxf(m0, mx0), mn1 = fmaxf(m1, mx1);
            const float a0 = __expf(m0 - mn0), a1 = __expf(m1 - mn1);
            float rs0 = 0.f, rs1 = 0.f;
            #pragma unroll
            for (int nn = 0; nn < 8; nn++) {
                float p0 = __expf(s[nn][0] - mn0);
                float p1 = __expf(s[nn][1] - mn0);
                float p2 = __expf(s[nn][2] - mn1);
                float p3 = __expf(s[nn][3] - mn1);
                s[nn][0] = p0; s[nn][1] = p1; s[nn][2] = p2; s[nn][3] = p3;
                rs0 += p0 + p1; rs1 += p2 + p3;
            }
            rs0 += __shfl_xor_sync(0xFFFFFFFFu, rs0, 1);
            rs0 += __shfl_xor_sync(0xFFFFFFFFu, rs0, 2);
            rs1 += __shfl_xor_sync(0xFFFFFFFFu, rs1, 1);
            rs1 += __shfl_xor_sync(0xFFFFFFFFu, rs1, 2);

            m0 = mn0; m1 = mn1;
            l0 = l0 * a0 + rs0;
            l1 = l1 * a1 + rs1;

            #pragma unroll
            for (int n = 0; n < 16; n++) {
                O[n][0] *= a0; O[n][1] *= a0;
                O[n][2] *= a1; O[n][3] *= a1;
            }

            #pragma unroll
            for (int kk = 0; kk < 4; kk++) {
                unsigned pa[4];
                pa[0] = bf2pack(s[2*kk][0],     s[2*kk][1]);
                pa[1] = bf2pack(s[2*kk][2],     s[2*kk][3]);
                pa[2] = bf2pack(s[2*kk + 1][0], s[2*kk + 1][1]);
                pa[3] = bf2pack(s[2*kk + 1][2], s[2*kk + 1][3]);
                #pragma unroll
                for (int ne = 0; ne < 8; ne++) {
                    int row = kk*16 + (g & 1)*8 + l7;
                    int col = ne*16 + (g >> 1)*8;
                    unsigned r[4];
                    ldsm4t(r, vBase + (row*FQP + col)*2);
                    mma16(O[2*ne],     pa, r);
                    mma16(O[2*ne + 1], pa, r + 2);
                }
            }
        }
    }

    const float inv0 = 1.f / l0, inv1 = 1.f / l1;
    __nv_bfloat16* Cg = ctx + ((size_t)(b * LL + qr0)) * HE + h * EE;
    #pragma unroll
    for (int n = 0; n < 16; n++) {
        const int c = n * 8 + lt * 2;
        *(unsigned*)(Cg + (size_t)lg       * HE + c) = bf2pack(O[n][0]*inv0, O[n][1]*inv0);
        *(unsigned*)(Cg + (size_t)(lg + 8) * HE + c) = bf2pack(O[n][2]*inv1, O[n][3]*inv1);
    }
}

// ============================================================
// Epilogue: out = LayerNorm(x + gelu_erf(ypre)) * gamma + beta
// float4 vectorized, one block per row.
// ============================================================
__global__ __launch_bounds__(256)
void epilogue_ln(const float* __restrict__ x, const float* __restrict__ ypre,
                 const float* __restrict__ gamma, const float* __restrict__ beta,
                 float* __restrict__ out)
{
    const int row = blockIdx.x;
    const int tid = threadIdx.x;
    const float4* xr4 = (const float4*)(x    + (size_t)row*DD);
    const float4* yr4 = (const float4*)(ypre + (size_t)row*DD);
    float4* out4      = (float4*)(out + (size_t)row*DD);

    float4 vals[2];
    float s = 0.f, s2 = 0.f;
    #pragma unroll
    for (int k = 0; k < 2; ++k) {
        const int c = tid + k*256;            // 512 float4s per row
        float4 v = yr4[c];
        float4 xv = xr4[c];
        float4 r;
        r.x = xv.x + 0.5f*v.x*(1.f + erff(v.x*0.70710678118654752f));
        r.y = xv.y + 0.5f*v.y*(1.f + erff(v.y*0.70710678118654752f));
        r.z = xv.z + 0.5f*v.z*(1.f + erff(v.z*0.70710678118654752f));
        r.w = xv.w + 0.5f*v.w*(1.f + erff(v.w*0.70710678118654752f));
        vals[k] = r;
        s  += r.x + r.y + r.z + r.w;
        s2 += r.x*r.x + r.y*r.y + r.z*r.z + r.w*r.w;
    }

    __shared__ float red[2][8];
    #pragma unroll
    for (int off = 16; off > 0; off >>= 1) {
        s  += __shfl_down_sync(0xFFFFFFFFu, s,  off);
        s2 += __shfl_down_sync(0xFFFFFFFFu, s2, off);
    }
    if ((tid & 31) == 0) { red[0][tid>>5] = s; red[1][tid>>5] = s2; }
    __syncthreads();
    float ts = 0.f, ts2 = 0.f;
    #pragma unroll
    for (int w = 0; w < 8; w++) { ts += red[0][w]; ts2 += red[1][w]; }

    const float mean = ts * (1.f/2048.f);
    const float var  = ts2 * (1.f/2048.f) - mean*mean;
    const float inv  = rsqrtf(var + 1e-5f);

    const float4* g4 = (const float4*)gamma;
    const float4* b4 = (const float4*)beta;
    #pragma unroll
    for (int k = 0; k < 2; ++k) {
        const int c = tid + k*256;
        float4 gv = g4[c], bv = b4[c], r = vals[k], o;
        o.x = (r.x - mean)*inv*gv.x + bv.x;
        o.y = (r.y - mean)*inv*gv.y + bv.y;
        o.z = (r.z - mean)*inv*gv.z + bv.z;
        o.w = (r.w - mean)*inv*gv.w + bv.w;
        out4[c] = o;
    }
}

// ============================================================
// Launch
// ============================================================
extern "C" void kernel_launch(void* const* d_in, const int* in_sizes, int n_in,
                              void* d_out, int out_size)
{
    const float* x     = (const float*)d_in[0];
    const float* Wq    = (const float*)d_in[1];
    const float* bq    = (const float*)d_in[2];
    const float* Wk    = (const float*)d_in[3];
    const float* bk    = (const float*)d_in[4];
    const float* Wv    = (const float*)d_in[5];
    const float* bv    = (const float*)d_in[6];
    const float* Wo    = (const float*)d_in[7];
    const float* bo    = (const float*)d_in[8];
    const float* gamma = (const float*)d_in[9];
    const float* beta  = (const float*)d_in[10];
    float* out = (float*)d_out;

    __nv_bfloat16 *xb, *Wqkvt, *Wot, *QKV, *CTXb;
    float *bqkv, *Y;
    cudaGetSymbolAddress((void**)&xb,    g_xb);
    cudaGetSymbolAddress((void**)&Wqkvt, g_Wqkvt);
    cudaGetSymbolAddress((void**)&Wot,   g_Wot);
    cudaGetSymbolAddress((void**)&bqkv,  g_bqkv);
    cudaGetSymbolAddress((void**)&QKV,   g_QKV);
    cudaGetSymbolAddress((void**)&CTXb,  g_CTXb);
    cudaGetSymbolAddress((void**)&Y,     g_Y);

    const dim3 blk(256);

    // ---- fused operand prep (single launch) ----
    prep_all<<<PREP_BLOCKS, blk>>>(x, Wq, Wk, Wv, Wo, bq, bk, bv,
                                   xb, Wqkvt, Wot, bqkv);

    // ---- fused QKV projection ----
    cudaFuncSetAttribute(gemm_bf16<true>,  cudaFuncAttributeMaxDynamicSharedMemorySize, GEMM_SMEM);
    cudaFuncSetAttribute(gemm_bf16<false>, cudaFuncAttributeMaxDynamicSharedMemorySize, GEMM_SMEM);
    gemm_bf16<true><<<dim3(QKVN/128, ML/128), blk, GEMM_SMEM>>>(xb, Wqkvt, bqkv, QKV,
                                                                ML, QKVN, DD, QKVN);

    // ---- causal GQA flash attention ----
    cudaFuncSetAttribute(flash_bf16, cudaFuncAttributeMaxDynamicSharedMemorySize, FL_SMEM_BYTES);
    flash_bf16<<<dim3(LL/128, BB*HH), blk, FL_SMEM_BYTES>>>(QKV, CTXb);

    // ---- output projection (fp32 out) ----
    gemm_bf16<false><<<dim3(DD/128, ML/128), blk, GEMM_SMEM>>>(CTXb, Wot, bo, Y,
                                                               ML, DD, HE, DD);

    // ---- GELU + residual + LayerNorm ----
    epilogue_ln<<<ML, 256>>>(x, Y, gamma, beta, out);
}